// round 13
// baseline (speedup 1.0000x reference)
#include <cuda_runtime.h>
#include <cuda_bf16.h>
#include <math.h>
#include <stdint.h>

// Problem constants
#define Bc 2
#define Lc 2048
#define Cc 1024
#define Hc 16
#define Dc 64
#define Mc (Bc*Lc)

// Scratch (device globals: allocation-free rule)
__device__ __nv_bfloat16 g_Xq_h[Mc*Cc], g_Xq_l[Mc*Cc];
__device__ __nv_bfloat16 g_Xk_h[Mc*Cc], g_Xk_l[Mc*Cc];
__device__ __nv_bfloat16 g_Xv_h[Mc*Cc], g_Xv_l[Mc*Cc];
__device__ __nv_bfloat16 g_Qb_h[Bc*Hc*Lc*Dc], g_Qb_l[Bc*Hc*Lc*Dc];
__device__ __nv_bfloat16 g_Kb_h[Bc*Hc*Lc*Dc], g_Kb_l[Bc*Hc*Lc*Dc];
__device__ __nv_bfloat16 g_Vb_h[Bc*Hc*Lc*Dc], g_Vb_l[Bc*Hc*Lc*Dc];
__device__ __nv_bfloat16 g_Zh[Bc*Lc*Cc], g_Zl[Bc*Lc*Cc];
__device__ __nv_bfloat16 g_Mb[Bc*Lc*Lc];

__device__ __nv_bfloat16 g_WtQ_h[Cc*Cc], g_WtQ_l[Cc*Cc];
__device__ __nv_bfloat16 g_WtK_h[Cc*Cc], g_WtK_l[Cc*Cc];
__device__ __nv_bfloat16 g_WtV_h[Cc*Cc], g_WtV_l[Cc*Cc];
__device__ __nv_bfloat16 g_WtO_h[Cc*Cc], g_WtO_l[Cc*Cc];

// ============================================================================
// Helpers
// ============================================================================
__device__ __forceinline__ uint32_t smem_u32(const void* p) {
    uint32_t a;
    asm("{ .reg .u64 t; cvta.to.shared.u64 t, %1; cvt.u32.u64 %0, t; }"
        : "=r"(a) : "l"(p));
    return a;
}
#define SWZ128(off) ((off) ^ (((off) >> 3) & 0x70))

#define CP16(dst, src) \
    asm volatile("cp.async.cg.shared.global [%0], [%1], 16;" \
                 :: "r"(dst), "l"(src) : "memory")
#define CP_COMMIT() asm volatile("cp.async.commit_group;" ::: "memory")
#define CP_WAIT1()  asm volatile("cp.async.wait_group 1;" ::: "memory")
#define CP_WAIT0()  asm volatile("cp.async.wait_group 0;" ::: "memory")

__device__ __forceinline__ void ldsm_x4(uint32_t* r, uint32_t addr) {
    asm volatile("ldmatrix.sync.aligned.m8n8.x4.shared.b16 {%0,%1,%2,%3}, [%4];"
                 : "=r"(r[0]), "=r"(r[1]), "=r"(r[2]), "=r"(r[3]) : "r"(addr));
}
__device__ __forceinline__ void ldsm_x4_t(uint32_t* r, uint32_t addr) {
    asm volatile("ldmatrix.sync.aligned.m8n8.x4.trans.shared.b16 {%0,%1,%2,%3}, [%4];"
                 : "=r"(r[0]), "=r"(r[1]), "=r"(r[2]), "=r"(r[3]) : "r"(addr));
}
__device__ __forceinline__ void mma_bf16(float* c, const uint32_t* a,
                                         const uint32_t* b) {
    asm volatile(
        "mma.sync.aligned.m16n8k16.row.col.f32.bf16.bf16.f32 "
        "{%0,%1,%2,%3}, {%4,%5,%6,%7}, {%8,%9}, {%0,%1,%2,%3};"
        : "+f"(c[0]), "+f"(c[1]), "+f"(c[2]), "+f"(c[3])
        : "r"(a[0]), "r"(a[1]), "r"(a[2]), "r"(a[3]), "r"(b[0]), "r"(b[1]));
}
__device__ __forceinline__ uint32_t pack_bf16(float x, float y) {
    __nv_bfloat162 v = __floats2bfloat162_rn(x, y);
    return *(uint32_t*)&v;
}
__device__ __forceinline__ float ex2f(float x) {
    float y;
    asm("ex2.approx.f32 %0, %1;" : "=f"(y) : "f"(x));
    return y;
}

// ============================================================================
// Prep kernels (fused)
// ============================================================================
struct XSplitBatch {
    const float* X[3];
    __nv_bfloat16 *Xh[3], *Xl[3];
};
__global__ void xsplit_kernel(XSplitBatch p)
{
    int z = blockIdx.y;
    size_t i = ((size_t)blockIdx.x * 256 + threadIdx.x) * 8;
    const float4* src = (const float4*)&p.X[z][i];
    float4 x0 = src[0], x1 = src[1];
    float xs[8] = {x0.x, x0.y, x0.z, x0.w, x1.x, x1.y, x1.z, x1.w};
    __nv_bfloat16 hh[8], ll[8];
#pragma unroll
    for (int e = 0; e < 8; e++) {
        hh[e] = __float2bfloat16_rn(xs[e]);
        ll[e] = __float2bfloat16_rn(xs[e] - __bfloat162float(hh[e]));
    }
    *(uint4*)&p.Xh[z][i] = *(uint4*)hh;
    *(uint4*)&p.Xl[z][i] = *(uint4*)ll;
}

struct WSplitBatch {
    const float* W[4];
    __nv_bfloat16 *Th[4], *Tl[4];
};
__global__ void wsplit_kernel(WSplitBatch p)
{
    __shared__ float tile[32][33];
    int z = blockIdx.z;
    int n0 = blockIdx.x * 32, k0 = blockIdx.y * 32;
    int tx = threadIdx.x, ty = threadIdx.y;
#pragma unroll
    for (int i = 0; i < 32; i += 8)
        tile[ty + i][tx] = p.W[z][(size_t)(k0 + ty + i) * Cc + n0 + tx];
    __syncthreads();
#pragma unroll
    for (int i = 0; i < 32; i += 8) {
        float x = tile[tx][ty + i];
        __nv_bfloat16 h = __float2bfloat16_rn(x);
        __nv_bfloat16 l = __float2bfloat16_rn(x - __bfloat162float(h));
        size_t idx = (size_t)(n0 + ty + i) * Cc + k0 + tx;
        p.Th[z][idx] = h; p.Tl[z][idx] = l;
    }
}

__global__ void maskprep_kernel(const int* __restrict__ m,
                                __nv_bfloat16* __restrict__ out)
{
    int i = (blockIdx.x * 256 + threadIdx.x) * 4;
    int4 v = *(const int4*)&m[i];
    __nv_bfloat162 a, b2;
    a.x  = __float2bfloat16_rn((float)(v.x - 1) * 2.0e9f);
    a.y  = __float2bfloat16_rn((float)(v.y - 1) * 2.0e9f);
    b2.x = __float2bfloat16_rn((float)(v.z - 1) * 2.0e9f);
    b2.y = __float2bfloat16_rn((float)(v.w - 1) * 2.0e9f);
    uint2 o; o.x = *(uint32_t*)&a; o.y = *(uint32_t*)&b2;
    *(uint2*)&out[i] = o;
}

// ============================================================================
// HMMA GEMM v6: CTA tile 256m x 128n, 8 warps (4x2), warp tile 64x64.
// Pass-separated MMA sweeps: per (ks, mf), three nf-sweeps (hh, hl, lh) of
// 8 independent MMAs each -> no RAW chains through accumulators.
// Per-acc contribution order unchanged -> bit-identical numerics.
// ============================================================================
#define G_BUFSZ 98304            // AH 32K | AL 32K | BH 16K | BL 16K
#define G_SMEM_TOTAL (2*G_BUFSZ) // 192 KB

template<int SPLITHEADS>
__device__ __forceinline__ void gemm_body(
    const __nv_bfloat16* __restrict__ Ah, const __nv_bfloat16* __restrict__ Al,
    const __nv_bfloat16* __restrict__ Bh, const __nv_bfloat16* __restrict__ Bl,
    const float* __restrict__ bias, float* __restrict__ Y,
    __nv_bfloat16* __restrict__ Yh, __nv_bfloat16* __restrict__ Yl,
    char* smem)
{
    const uint32_t sb = smem_u32(smem);
    const int t     = threadIdx.x;
    const int wid   = t >> 5;
    const int lane  = t & 31;
    const int warpM = wid & 3;
    const int warpN = wid >> 2;
    const int n0    = blockIdx.x * 128;
    const int m0    = blockIdx.y * 256;

    auto stage = [&](int s) {
        const int k0 = s * 64;
        const uint32_t bufb = sb + (s & 1) * G_BUFSZ;
#pragma unroll
        for (int u = 0; u < 16; u++) {
            int seg = t + u * 256;
            int arr = seg >> 11;
            int s2  = seg & 2047;
            int r   = s2 >> 3, c = s2 & 7;
            const __nv_bfloat16* g = (arr ? Al : Ah) + (size_t)(m0 + r) * 1024 + k0 + c * 8;
            uint32_t dst = bufb + arr * 32768 + SWZ128((uint32_t)(r * 128 + c * 16));
            CP16(dst, g);
        }
#pragma unroll
        for (int u = 0; u < 8; u++) {
            int seg = t + u * 256;
            int arr = seg >> 10;
            int s2  = seg & 1023;
            int r   = s2 >> 3, c = s2 & 7;
            const __nv_bfloat16* g = (arr ? Bl : Bh) + (size_t)(n0 + r) * 1024 + k0 + c * 8;
            uint32_t dst = bufb + 65536 + arr * 16384 + SWZ128((uint32_t)(r * 128 + c * 16));
            CP16(dst, g);
        }
        CP_COMMIT();
    };

    float acc[4][8][4];
#pragma unroll
    for (int mf = 0; mf < 4; mf++)
#pragma unroll
        for (int nf = 0; nf < 8; nf++)
#pragma unroll
            for (int e = 0; e < 4; e++) acc[mf][nf][e] = 0.f;

    const int mat   = lane >> 3;
    const int r8    = lane & 7;
    const int aRow0 = warpM * 64 + (mat & 1) * 8 + r8;
    const int aKh   = mat >> 1;
    const int bRow0 = warpN * 64 + (mat >> 1) * 8 + r8;
    const int bKh   = mat & 1;

    stage(0);

    for (int s = 0; s < 16; s++) {
        if (s + 1 < 16) { stage(s + 1); CP_WAIT1(); }
        else            { CP_WAIT0(); }
        __syncthreads();

        const uint32_t AH = sb + (s & 1) * G_BUFSZ;
        const uint32_t AL = AH + 32768, BH = AH + 65536, BL = AH + 81920;

#pragma unroll
        for (int ks = 0; ks < 4; ks++) {
            // All B fragments for this ks
            uint32_t bHf[4][4], bLf[4][4];
#pragma unroll
            for (int g = 0; g < 4; g++) {
                int row = bRow0 + g * 16;
                uint32_t off = (uint32_t)(row * 128 +
                               (((2 * ks + bKh) ^ (row & 7)) * 16));
                ldsm_x4(bHf[g], BH + off);
                ldsm_x4(bLf[g], BL + off);
            }
#pragma unroll
            for (int mf = 0; mf < 4; mf++) {
                uint32_t aH[4], aL[4];
                int row = aRow0 + mf * 16;
                uint32_t off = (uint32_t)(row * 128 +
                               (((2 * ks + aKh) ^ (row & 7)) * 16));
                ldsm_x4(aH, AH + off);
                ldsm_x4(aL, AL + off);
                // Pass 0: aH * Bh  (8 independent MMAs)
#pragma unroll
                for (int nf = 0; nf < 8; nf++)
                    mma_bf16(acc[mf][nf], aH, &bHf[nf >> 1][(nf & 1) * 2]);
                // Pass 1: aH * Bl
#pragma unroll
                for (int nf = 0; nf < 8; nf++)
                    mma_bf16(acc[mf][nf], aH, &bLf[nf >> 1][(nf & 1) * 2]);
                // Pass 2: aL * Bh
#pragma unroll
                for (int nf = 0; nf < 8; nf++)
                    mma_bf16(acc[mf][nf], aL, &bHf[nf >> 1][(nf & 1) * 2]);
            }
        }
        __syncthreads();
    }

    const int rbase = lane >> 2;
    const int cpair = (lane & 3) * 2;
#pragma unroll
    for (int nf = 0; nf < 8; nf++) {
        int n = n0 + warpN * 64 + nf * 8 + cpair;
        float bx = __ldg(&bias[n]), by = __ldg(&bias[n + 1]);
#pragma unroll
        for (int mf = 0; mf < 4; mf++) {
            float* a = acc[mf][nf];
            int m = m0 + warpM * 64 + mf * 16 + rbase;
#pragma unroll
            for (int half = 0; half < 2; half++) {
                int mm = m + half * 8;
                float vx = a[half * 2 + 0] + bx, vy = a[half * 2 + 1] + by;
                if (SPLITHEADS) {
                    int b = mm >> 11, l = mm & 2047;
                    int h = n >> 6,  d = n & 63;
                    size_t idx = (((size_t)(b * Hc + h)) * Lc + l) * Dc + d;
                    __nv_bfloat162 hv = __floats2bfloat162_rn(vx, vy);
                    __nv_bfloat162 lv = __floats2bfloat162_rn(
                        vx - __bfloat162float(hv.x), vy - __bfloat162float(hv.y));
                    *(uint32_t*)&Yh[idx] = *(uint32_t*)&hv;
                    *(uint32_t*)&Yl[idx] = *(uint32_t*)&lv;
                } else {
                    *(float2*)&Y[(size_t)mm * 1024 + n] = make_float2(vx, vy);
                }
            }
        }
    }
}

struct GemmBatch {
    const __nv_bfloat16 *Ah[3], *Al[3], *Bh[3], *Bl[3];
    const float* bias[3];
    __nv_bfloat16 *Yh[3], *Yl[3];
};

__global__ void __launch_bounds__(256, 1) gemm_proj_kernel(GemmBatch p)
{
    extern __shared__ char smem[];
    int z = blockIdx.z;
    gemm_body<1>(p.Ah[z], p.Al[z], p.Bh[z], p.Bl[z], p.bias[z],
                 nullptr, p.Yh[z], p.Yl[z], smem);
}

__global__ void __launch_bounds__(256, 1)
gemm_out_kernel(const __nv_bfloat16* Ah, const __nv_bfloat16* Al,
                const __nv_bfloat16* Bh, const __nv_bfloat16* Bl,
                const float* bias, float* Y)
{
    extern __shared__ char smem[];
    gemm_body<0>(Ah, Al, Bh, Bl, bias, Y, nullptr, nullptr, smem);
}

// ============================================================================
// HMMA flash attention v6 (unchanged from R10/R11): 256q/CTA, 32 q-rows/warp.
// ============================================================================
#define ATT_QH 0
#define ATT_QL 32768
#define ATT_B0 65536
#define ATT_KVBUF 32768
#define ATT_MS0 131072
#define ATT_MSBUF 36864
#define ATT_SMEM 204800

__global__ void __launch_bounds__(256, 1)
attn_mma_kernel(const __nv_bfloat16* __restrict__ Qh, const __nv_bfloat16* __restrict__ Ql,
                const __nv_bfloat16* __restrict__ Kh, const __nv_bfloat16* __restrict__ Kl,
                const __nv_bfloat16* __restrict__ Vh, const __nv_bfloat16* __restrict__ Vl,
                const __nv_bfloat16* __restrict__ Mb,
                __nv_bfloat16* __restrict__ Zh, __nv_bfloat16* __restrict__ Zl)
{
    extern __shared__ char smem[];
    const uint32_t sb = smem_u32(smem);
    const int t  = threadIdx.x;
    const int w  = t >> 5;
    const int l  = t & 31;
    const int bh = blockIdx.y;
    const int b  = bh >> 4;
    const int h  = bh & 15;
    const int q0 = blockIdx.x * 256;

    const __nv_bfloat16* Qbh = Qh + (size_t)bh * Lc * Dc;
    const __nv_bfloat16* Qbl = Ql + (size_t)bh * Lc * Dc;
    const __nv_bfloat16* Kbh = Kh + (size_t)bh * Lc * Dc;
    const __nv_bfloat16* Kbl = Kl + (size_t)bh * Lc * Dc;
    const __nv_bfloat16* Vbh = Vh + (size_t)bh * Lc * Dc;
    const __nv_bfloat16* Vbl = Vl + (size_t)bh * Lc * Dc;
    const __nv_bfloat16* Mbb = Mb + ((size_t)b * Lc + q0) * Lc;

    const float SC = 0.125f * 1.4426950408889634f;
    const int mat = l >> 3;
    const int r8  = l & 7;
    const int gr  = l >> 2;

    const __nv_bfloat16* kvsrc[4] = {Kbh, Kbl, Vbh, Vbl};

    auto stage = [&](int s) {
        const int kt = s * 64;
        const uint32_t kvb = sb + ATT_B0 + (s & 1) * ATT_KVBUF;
        const uint32_t msb = sb + ATT_MS0 + (s & 1) * ATT_MSBUF;
#pragma unroll
        for (int u = 0; u < 8; u++) {
            int seg = t + u * 256;
            int arr = seg >> 9;
            int s2  = seg & 511;
            int r   = s2 >> 3, c = s2 & 7;
            const __nv_bfloat16* g = kvsrc[arr] + (size_t)(kt + r) * Dc + c * 8;
            uint32_t dst = kvb + arr * 8192 + SWZ128((uint32_t)(r * 128 + c * 16));
            CP16(dst, g);
        }
#pragma unroll
        for (int u = 0; u < 8; u++) {
            int seg = t + u * 256;
            int r = seg >> 3, c = seg & 7;
            const __nv_bfloat16* g = Mbb + (size_t)r * Lc + kt + c * 8;
            CP16(msb + r * 144 + c * 16, g);
        }
        CP_COMMIT();
    };

#pragma unroll
    for (int u = 0; u < 16; u++) {
        int seg = t + u * 256;
        int arr = seg >> 11;
        int s2  = seg & 2047;
        int r   = s2 >> 3, c = s2 & 7;
        const __nv_bfloat16* g = (arr ? Qbl : Qbh) + (size_t)(q0 + r) * Dc + c * 8;
        uint32_t dst = sb + (arr ? ATT_QL : ATT_QH) + SWZ128((uint32_t)(r * 128 + c * 16));
        CP16(dst, g);
    }
    stage(0);

    float accO[2][8][4];
#pragma unroll
    for (int mf = 0; mf < 2; mf++)
#pragma unroll
        for (int nf = 0; nf < 8; nf++)
#pragma unroll
            for (int e = 0; e < 4; e++) accO[mf][nf][e] = 0.f;
    float mA[2] = {-3.0e38f, -3.0e38f}, mB[2] = {-3.0e38f, -3.0e38f};
    float lA[2] = {0.f, 0.f},           lB[2] = {0.f, 0.f};

    for (int s = 0; s < 32; s++) {
        if (s + 1 < 32) { stage(s + 1); CP_WAIT1(); }
        else            { CP_WAIT0(); }
        __syncthreads();

        const uint32_t KHb = sb + ATT_B0 + (s & 1) * ATT_KVBUF;
        const uint32_t KLb = KHb + 8192, VHb = KHb + 16384, VLb = KHb + 24576;
        const uint32_t MSo = ATT_MS0 + (s & 1) * ATT_MSBUF;

        float accS[2][8][4];
#pragma unroll
        for (int mf = 0; mf < 2; mf++)
#pragma unroll
            for (int nf = 0; nf < 8; nf++)
#pragma unroll
                for (int e = 0; e < 4; e++) accS[mf][nf][e] = 0.f;

#pragma unroll
        for (int kf = 0; kf < 4; kf++) {
            uint32_t qh[2][4], ql[2][4];
#pragma unroll
            for (int mf = 0; mf < 2; mf++) {
                int row = w * 32 + mf * 16 + (mat & 1) * 8 + r8;
                int chk = kf * 2 + (mat >> 1);
                uint32_t off = (uint32_t)(row * 128 + ((chk ^ (row & 7)) * 16));
                ldsm_x4(qh[mf], sb + ATT_QH + off);
                ldsm_x4(ql[mf], sb + ATT_QL + off);
            }
#pragma unroll
            for (int g = 0; g < 4; g++) {
                uint32_t kh[4], kl[4];
                int row = g * 16 + (mat >> 1) * 8 + r8;
                int chk = kf * 2 + (mat & 1);
                uint32_t off = (uint32_t)(row * 128 + ((chk ^ (row & 7)) * 16));
                ldsm_x4(kh, KHb + off);
                ldsm_x4(kl, KLb + off);
#pragma unroll
                for (int mf = 0; mf < 2; mf++) {
                    mma_bf16(accS[mf][2 * g],     qh[mf], kh);
                    mma_bf16(accS[mf][2 * g],     qh[mf], kl);
                    mma_bf16(accS[mf][2 * g],     ql[mf], kh);
                    mma_bf16(accS[mf][2 * g + 1], qh[mf], kh + 2);
                    mma_bf16(accS[mf][2 * g + 1], qh[mf], kl + 2);
                    mma_bf16(accS[mf][2 * g + 1], ql[mf], kh + 2);
                }
            }
        }

#pragma unroll
        for (int mf = 0; mf < 2; mf++) {
            const int rw0 = w * 32 + mf * 16 + gr;
            float t0 = -3.0e38f, t1 = -3.0e38f;
#pragma unroll
            for (int nf = 0; nf < 8; nf++) {
                int colb = (nf * 8 + (l & 3) * 2) * 2;
                __nv_bfloat162 ms0 = *(__nv_bfloat162*)(smem + MSo + rw0 * 144 + colb);
                __nv_bfloat162 ms1 = *(__nv_bfloat162*)(smem + MSo + (rw0 + 8) * 144 + colb);
                accS[mf][nf][0] = fmaf(accS[mf][nf][0], SC, __bfloat162float(ms0.x));
                accS[mf][nf][1] = fmaf(accS[mf][nf][1], SC, __bfloat162float(ms0.y));
                accS[mf][nf][2] = fmaf(accS[mf][nf][2], SC, __bfloat162float(ms1.x));
                accS[mf][nf][3] = fmaf(accS[mf][nf][3], SC, __bfloat162float(ms1.y));
                t0 = fmaxf(t0, fmaxf(accS[mf][nf][0], accS[mf][nf][1]));
                t1 = fmaxf(t1, fmaxf(accS[mf][nf][2], accS[mf][nf][3]));
            }
            t0 = fmaxf(t0, __shfl_xor_sync(0xffffffffu, t0, 1));
            t0 = fmaxf(t0, __shfl_xor_sync(0xffffffffu, t0, 2));
            t1 = fmaxf(t1, __shfl_xor_sync(0xffffffffu, t1, 1));
            t1 = fmaxf(t1, __shfl_xor_sync(0xffffffffu, t1, 2));

            float mn0 = fmaxf(mA[mf], t0), mn1 = fmaxf(mB[mf], t1);
            float f0 = ex2f(mA[mf] - mn0), f1 = ex2f(mB[mf] - mn1);
            mA[mf] = mn0; mB[mf] = mn1;

            float rs0 = 0.f, rs1 = 0.f;
#pragma unroll
            for (int nf = 0; nf < 8; nf++) {
                accS[mf][nf][0] = ex2f(accS[mf][nf][0] - mA[mf]);
                accS[mf][nf][1] = ex2f(accS[mf][nf][1] - mA[mf]);
                accS[mf][nf][2] = ex2f(accS[mf][nf][2] - mB[mf]);
                accS[mf][nf][3] = ex2f(accS[mf][nf][3] - mB[mf]);
                rs0 += accS[mf][nf][0] + accS[mf][nf][1];
                rs1 += accS[mf][nf][2] + accS[mf][nf][3];
                accO[mf][nf][0] *= f0; accO[mf][nf][1] *= f0;
                accO[mf][nf][2] *= f1; accO[mf][nf][3] *= f1;
            }
            rs0 += __shfl_xor_sync(0xffffffffu, rs0, 1);
            rs0 += __shfl_xor_sync(0xffffffffu, rs0, 2);
            rs1 += __shfl_xor_sync(0xffffffffu, rs1, 1);
            rs1 += __shfl_xor_sync(0xffffffffu, rs1, 2);
            lA[mf] = lA[mf] * f0 + rs0;
            lB[mf] = lB[mf] * f1 + rs1;
        }

#pragma unroll
        for (int kf = 0; kf < 4; kf++) {
            uint32_t ah[2][4], al[2][4];
#pragma unroll
            for (int mf = 0; mf < 2; mf++) {
                const float* pA = accS[mf][2 * kf];
                const float* pB = accS[mf][2 * kf + 1];
                float ev[8] = {pA[0], pA[1], pA[2], pA[3],
                               pB[0], pB[1], pB[2], pB[3]};
#pragma unroll
                for (int i = 0; i < 4; i++) {
                    float x = ev[2 * i], y = ev[2 * i + 1];
                    __nv_bfloat16 xh = __float2bfloat16_rn(x);
                    __nv_bfloat16 yh = __float2bfloat16_rn(y);
                    ah[mf][i] = pack_bf16(x, y);
                    al[mf][i] = pack_bf16(x - __bfloat162float(xh),
                                          y - __bfloat162float(yh));
                }
            }
            int rowv = kf * 16 + (l & 15);
#pragma unroll
            for (int g = 0; g < 4; g++) {
                uint32_t vh[4], vl[4];
                int chv = g * 2 + (l >> 4);
                uint32_t off = (uint32_t)(rowv * 128 + ((chv ^ (rowv & 7)) * 16));
                ldsm_x4_t(vh, VHb + off);
                ldsm_x4_t(vl, VLb + off);
#pragma unroll
                for (int mf = 0; mf < 2; mf++) {
                    mma_bf16(accO[mf][2 * g],     ah[mf], vh);
                    mma_bf16(accO[mf][2 * g],     ah[mf], vl);
                    mma_bf16(accO[mf][2 * g],     al[mf], vh);
                    mma_bf16(accO[mf][2 * g + 1], ah[mf], vh + 2);
                    mma_bf16(accO[mf][2 * g + 1], ah[mf], vl + 2);
                    mma_bf16(accO[mf][2 * g + 1], al[mf], vh + 2);
                }
            }
        }
        __syncthreads();
    }

#pragma unroll
    for (int mf = 0; mf < 2; mf++) {
        float inv0 = 1.f / lA[mf], inv1 = 1.f / lB[mf];
        int qg0 = q0 + w * 32 + mf * 16 + gr;
#pragma unroll
        for (int nf = 0; nf < 8; nf++) {
            int d = nf * 8 + (l & 3) * 2;
            float x0 = accO[mf][nf][0] * inv0, y0 = accO[mf][nf][1] * inv0;
            float x1 = accO[mf][nf][2] * inv1, y1 = accO[mf][nf][3] * inv1;
            size_t i0 = ((size_t)(b * Lc + qg0)) * Cc + h * 64 + d;
            size_t i1 = ((size_t)(b * Lc + qg0 + 8)) * Cc + h * 64 + d;
            __nv_bfloat162 h0 = __floats2bfloat162_rn(x0, y0);
            __nv_bfloat162 l0 = __floats2bfloat162_rn(
                x0 - __bfloat162float(h0.x), y0 - __bfloat162float(h0.y));
            __nv_bfloat162 h1 = __floats2bfloat162_rn(x1, y1);
            __nv_bfloat162 l1 = __floats2bfloat162_rn(
                x1 - __bfloat162float(h1.x), y1 - __bfloat162float(h1.y));
            *(uint32_t*)&Zh[i0] = *(uint32_t*)&h0;
            *(uint32_t*)&Zl[i0] = *(uint32_t*)&l0;
            *(uint32_t*)&Zh[i1] = *(uint32_t*)&h1;
            *(uint32_t*)&Zl[i1] = *(uint32_t*)&l1;
        }
    }
}

// ============================================================================
// Launcher
// ============================================================================
extern "C" void kernel_launch(void* const* d_in, const int* in_sizes, int n_in,
                              void* d_out, int out_size)
{
    const float* query = (const float*)d_in[0];
    const float* key_  = (const float*)d_in[1];
    const float* value = (const float*)d_in[2];
    const int*   mask  = (const int*)  d_in[3];
    const float* WQ = (const float*)d_in[4];
    const float* bQ = (const float*)d_in[5];
    const float* WK = (const float*)d_in[6];
    const float* bK = (const float*)d_in[7];
    const float* WV = (const float*)d_in[8];
    const float* bV = (const float*)d_in[9];
    const float* WO = (const float*)d_in[10];
    const float* bO = (const float*)d_in[11];
    float* out = (float*)d_out;

    void *xqh, *xql, *xkh, *xkl, *xvh, *xvl;
    cudaGetSymbolAddress(&xqh, g_Xq_h); cudaGetSymbolAddress(&xql, g_Xq_l);
    cudaGetSymbolAddress(&xkh, g_Xk_h); cudaGetSymbolAddress(&xkl, g_Xk_l);
    cudaGetSymbolAddress(&xvh, g_Xv_h); cudaGetSymbolAddress(&xvl, g_Xv_l);
    void *qbh, *qbl, *kbh, *kbl, *vbh, *vbl, *zh, *zl, *pM;
    cudaGetSymbolAddress(&qbh, g_Qb_h); cudaGetSymbolAddress(&qbl, g_Qb_l);
    cudaGetSymbolAddress(&kbh, g_Kb_h); cudaGetSymbolAddress(&kbl, g_Kb_l);
    cudaGetSymbolAddress(&vbh, g_Vb_h); cudaGetSymbolAddress(&vbl, g_Vb_l);
    cudaGetSymbolAddress(&zh, g_Zh);    cudaGetSymbolAddress(&zl, g_Zl);
    cudaGetSymbolAddress(&pM, g_Mb);
    void *wqh, *wql, *wkh, *wkl, *wvh, *wvl, *woh, *wol;
    cudaGetSymbolAddress(&wqh, g_WtQ_h); cudaGetSymbolAddress(&wql, g_WtQ_l);
    cudaGetSymbolAddress(&wkh, g_WtK_h); cudaGetSymbolAddress(&wkl, g_WtK_l);
    cudaGetSymbolAddress(&wvh, g_WtV_h); cudaGetSymbolAddress(&wvl, g_WtV_l);
    cudaGetSymbolAddress(&woh, g_WtO_h); cudaGetSymbolAddress(&wol, g_WtO_l);

    cudaFuncSetAttribute(attn_mma_kernel,
                         cudaFuncAttributeMaxDynamicSharedMemorySize, ATT_SMEM);
    cudaFuncSetAttribute(gemm_proj_kernel,
                         cudaFuncAttributeMaxDynamicSharedMemorySize, G_SMEM_TOTAL);
    cudaFuncSetAttribute(gemm_out_kernel,
                         cudaFuncAttributeMaxDynamicSharedMemorySize, G_SMEM_TOTAL);

    // --- Prep (fused) ---
    XSplitBatch xp;
    xp.X[0] = query; xp.X[1] = key_; xp.X[2] = value;
    xp.Xh[0] = (__nv_bfloat16*)xqh; xp.Xl[0] = (__nv_bfloat16*)xql;
    xp.Xh[1] = (__nv_bfloat16*)xkh; xp.Xl[1] = (__nv_bfloat16*)xkl;
    xp.Xh[2] = (__nv_bfloat16*)xvh; xp.Xl[2] = (__nv_bfloat16*)xvl;
    xsplit_kernel<<<dim3(Mc * Cc / (256 * 8), 3), 256>>>(xp);

    maskprep_kernel<<<(Bc * Lc * Lc) / (256 * 4), 256>>>(mask, (__nv_bfloat16*)pM);

    WSplitBatch wp;
    wp.W[0] = WQ; wp.W[1] = WK; wp.W[2] = WV; wp.W[3] = WO;
    wp.Th[0] = (__nv_bfloat16*)wqh; wp.Tl[0] = (__nv_bfloat16*)wql;
    wp.Th[1] = (__nv_bfloat16*)wkh; wp.Tl[1] = (__nv_bfloat16*)wkl;
    wp.Th[2] = (__nv_bfloat16*)wvh; wp.Tl[2] = (__nv_bfloat16*)wvl;
    wp.Th[3] = (__nv_bfloat16*)woh; wp.Tl[3] = (__nv_bfloat16*)wol;
    wsplit_kernel<<<dim3(32, 32, 4), dim3(32, 8)>>>(wp);

    // --- Fused projection GEMMs (256m x 128n tiles) ---
    GemmBatch gp;
    gp.Ah[0] = (const __nv_bfloat16*)xqh; gp.Al[0] = (const __nv_bfloat16*)xql;
    gp.Ah[1] = (const __nv_bfloat16*)xkh; gp.Al[1] = (const __nv_bfloat16*)xkl;
    gp.Ah[2] = (const __nv_bfloat16*)xvh; gp.Al[2] = (const __nv_bfloat16*)xvl;
    gp.Bh[0] = (const __nv_bfloat16*)wqh; gp.Bl[0] = (const __nv_bfloat16*)wql;
    gp.Bh[1] = (const __nv_bfloat16*)wkh; gp.Bl[1] = (const __nv_bfloat16*)wkl;
    gp.Bh[2] = (const __nv_bfloat16*)wvh; gp.Bl[2] = (const __nv_bfloat16*)wvl;
    gp.bias[0] = bQ; gp.bias[1] = bK; gp.bias[2] = bV;
    gp.Yh[0] = (__nv_bfloat16*)qbh; gp.Yl[0] = (__nv_bfloat16*)qbl;
    gp.Yh[1] = (__nv_bfloat16*)kbh; gp.Yl[1] = (__nv_bfloat16*)kbl;
    gp.Yh[2] = (__nv_bfloat16*)vbh; gp.Yl[2] = (__nv_bfloat16*)vbl;
    gemm_proj_kernel<<<dim3(Cc / 128, Mc / 256, 3), 256, G_SMEM_TOTAL>>>(gp);

    dim3 attn_grid(Lc / 256, Bc * Hc);
    attn_mma_kernel<<<attn_grid, 256, ATT_SMEM>>>(
        (const __nv_bfloat16*)qbh, (const __nv_bfloat16*)qbl,
        (const __nv_bfloat16*)kbh, (const __nv_bfloat16*)kbl,
        (const __nv_bfloat16*)vbh, (const __nv_bfloat16*)vbl,
        (const __nv_bfloat16*)pM, (__nv_bfloat16*)zh, (__nv_bfloat16*)zl);

    gemm_out_kernel<<<dim3(Cc / 128, Mc / 256), 256, G_SMEM_TOTAL>>>(
        (const __nv_bfloat16*)zh, (const __nv_bfloat16*)zl,
        (const __nv_bfloat16*)woh, (const __nv_bfloat16*)wol, bO, out);
}

// round 14
// speedup vs baseline: 1.1443x; 1.1443x over previous
#include <cuda_runtime.h>
#include <cuda_bf16.h>
#include <cuda_fp16.h>
#include <math.h>
#include <stdint.h>

// Problem constants
#define Bc 2
#define Lc 2048
#define Cc 1024
#define Hc 16
#define Dc 64
#define Mc (Bc*Lc)

// Scratch (device globals: allocation-free rule)
__device__ __half g_Xq_h[Mc*Cc], g_Xq_l[Mc*Cc];   // fp16 hi/lo activations
__device__ __half g_Xk_h[Mc*Cc], g_Xk_l[Mc*Cc];
__device__ __half g_Xv_h[Mc*Cc], g_Xv_l[Mc*Cc];
__device__ __nv_bfloat16 g_Qb_h[Bc*Hc*Lc*Dc], g_Qb_l[Bc*Hc*Lc*Dc];
__device__ __nv_bfloat16 g_Kb_h[Bc*Hc*Lc*Dc], g_Kb_l[Bc*Hc*Lc*Dc];
__device__ __nv_bfloat16 g_Vb_h[Bc*Hc*Lc*Dc], g_Vb_l[Bc*Hc*Lc*Dc];
__device__ __half g_Zh[Bc*Lc*Cc], g_Zl[Bc*Lc*Cc];  // fp16 hi/lo Z
__device__ __nv_bfloat16 g_Mb[Bc*Lc*Lc];

// Single fp16 weights, transposed [N][K]
__device__ __half g_WtQ[Cc*Cc];
__device__ __half g_WtK[Cc*Cc];
__device__ __half g_WtV[Cc*Cc];
__device__ __half g_WtO[Cc*Cc];

// ============================================================================
// Helpers
// ============================================================================
__device__ __forceinline__ uint32_t smem_u32(const void* p) {
    uint32_t a;
    asm("{ .reg .u64 t; cvta.to.shared.u64 t, %1; cvt.u32.u64 %0, t; }"
        : "=r"(a) : "l"(p));
    return a;
}
#define SWZ128(off) ((off) ^ (((off) >> 3) & 0x70))

#define CP16(dst, src) \
    asm volatile("cp.async.cg.shared.global [%0], [%1], 16;" \
                 :: "r"(dst), "l"(src) : "memory")
#define CP_COMMIT() asm volatile("cp.async.commit_group;" ::: "memory")
#define CP_WAIT1()  asm volatile("cp.async.wait_group 1;" ::: "memory")
#define CP_WAIT0()  asm volatile("cp.async.wait_group 0;" ::: "memory")

__device__ __forceinline__ void ldsm_x4(uint32_t* r, uint32_t addr) {
    asm volatile("ldmatrix.sync.aligned.m8n8.x4.shared.b16 {%0,%1,%2,%3}, [%4];"
                 : "=r"(r[0]), "=r"(r[1]), "=r"(r[2]), "=r"(r[3]) : "r"(addr));
}
__device__ __forceinline__ void ldsm_x4_t(uint32_t* r, uint32_t addr) {
    asm volatile("ldmatrix.sync.aligned.m8n8.x4.trans.shared.b16 {%0,%1,%2,%3}, [%4];"
                 : "=r"(r[0]), "=r"(r[1]), "=r"(r[2]), "=r"(r[3]) : "r"(addr));
}
__device__ __forceinline__ void mma_bf16(float* c, const uint32_t* a,
                                         const uint32_t* b) {
    asm volatile(
        "mma.sync.aligned.m16n8k16.row.col.f32.bf16.bf16.f32 "
        "{%0,%1,%2,%3}, {%4,%5,%6,%7}, {%8,%9}, {%0,%1,%2,%3};"
        : "+f"(c[0]), "+f"(c[1]), "+f"(c[2]), "+f"(c[3])
        : "r"(a[0]), "r"(a[1]), "r"(a[2]), "r"(a[3]), "r"(b[0]), "r"(b[1]));
}
__device__ __forceinline__ void mma_f16(float* c, const uint32_t* a,
                                        const uint32_t* b) {
    asm volatile(
        "mma.sync.aligned.m16n8k16.row.col.f32.f16.f16.f32 "
        "{%0,%1,%2,%3}, {%4,%5,%6,%7}, {%8,%9}, {%0,%1,%2,%3};"
        : "+f"(c[0]), "+f"(c[1]), "+f"(c[2]), "+f"(c[3])
        : "r"(a[0]), "r"(a[1]), "r"(a[2]), "r"(a[3]), "r"(b[0]), "r"(b[1]));
}
__device__ __forceinline__ uint32_t pack_bf16(float x, float y) {
    __nv_bfloat162 v = __floats2bfloat162_rn(x, y);
    return *(uint32_t*)&v;
}
__device__ __forceinline__ float ex2f(float x) {
    float y;
    asm("ex2.approx.f32 %0, %1;" : "=f"(y) : "f"(x));
    return y;
}

// ============================================================================
// Prep kernels
// ============================================================================
struct XSplitBatch {
    const float* X[3];
    __half *Xh[3], *Xl[3];
};
__global__ void xsplit_kernel(XSplitBatch p)
{
    int z = blockIdx.y;
    size_t i = ((size_t)blockIdx.x * 256 + threadIdx.x) * 8;
    const float4* src = (const float4*)&p.X[z][i];
    float4 x0 = src[0], x1 = src[1];
    float xs[8] = {x0.x, x0.y, x0.z, x0.w, x1.x, x1.y, x1.z, x1.w};
    __half hh[8], ll[8];
#pragma unroll
    for (int e = 0; e < 8; e++) {
        hh[e] = __float2half_rn(xs[e]);
        ll[e] = __float2half_rn(xs[e] - __half2float(hh[e]));
    }
    *(uint4*)&p.Xh[z][i] = *(uint4*)hh;
    *(uint4*)&p.Xl[z][i] = *(uint4*)ll;
}

struct WSplitBatch {
    const float* W[4];
    __half* T[4];
};
__global__ void wsplit_kernel(WSplitBatch p)
{
    __shared__ float tile[32][33];
    int z = blockIdx.z;
    int n0 = blockIdx.x * 32, k0 = blockIdx.y * 32;
    int tx = threadIdx.x, ty = threadIdx.y;
#pragma unroll
    for (int i = 0; i < 32; i += 8)
        tile[ty + i][tx] = p.W[z][(size_t)(k0 + ty + i) * Cc + n0 + tx];
    __syncthreads();
#pragma unroll
    for (int i = 0; i < 32; i += 8) {
        size_t idx = (size_t)(n0 + ty + i) * Cc + k0 + tx;
        p.T[z][idx] = __float2half_rn(tile[tx][ty + i]);
    }
}

__global__ void maskprep_kernel(const int* __restrict__ m,
                                __nv_bfloat16* __restrict__ out)
{
    int i = (blockIdx.x * 256 + threadIdx.x) * 4;
    int4 v = *(const int4*)&m[i];
    __nv_bfloat162 a, b2;
    a.x  = __float2bfloat16_rn((float)(v.x - 1) * 2.0e9f);
    a.y  = __float2bfloat16_rn((float)(v.y - 1) * 2.0e9f);
    b2.x = __float2bfloat16_rn((float)(v.z - 1) * 2.0e9f);
    b2.y = __float2bfloat16_rn((float)(v.w - 1) * 2.0e9f);
    uint2 o; o.x = *(uint32_t*)&a; o.y = *(uint32_t*)&b2;
    *(uint2*)&out[i] = o;
}

// ============================================================================
// HMMA GEMM v7 (fp16 2-pass): Y = (Ah+Al) @ B^T + bias, A fp16 hi/lo,
// B single fp16. CTA tile 256m x 128n, 8 warps (4x2), warp tile 64x64.
// 16 MMAs per (ks,mf) instead of 24.
// ============================================================================
#define G_BUFSZ 81920            // AH 32K | AL 32K | BS 16K
#define G_SMEM_TOTAL (2*G_BUFSZ) // 160 KB

template<int SPLITHEADS>
__device__ __forceinline__ void gemm_body(
    const __half* __restrict__ Ah, const __half* __restrict__ Al,
    const __half* __restrict__ Bs,
    const float* __restrict__ bias, float* __restrict__ Y,
    __nv_bfloat16* __restrict__ Yh, __nv_bfloat16* __restrict__ Yl,
    char* smem)
{
    const uint32_t sb = smem_u32(smem);
    const int t     = threadIdx.x;
    const int wid   = t >> 5;
    const int lane  = t & 31;
    const int warpM = wid & 3;
    const int warpN = wid >> 2;
    const int n0    = blockIdx.x * 128;
    const int m0    = blockIdx.y * 256;

    auto stage = [&](int s) {
        const int k0 = s * 64;
        const uint32_t bufb = sb + (s & 1) * G_BUFSZ;
        // A: 2 arrays x 256 rows x 8 chunks = 4096 -> 16/thread
#pragma unroll
        for (int u = 0; u < 16; u++) {
            int seg = t + u * 256;
            int arr = seg >> 11;
            int s2  = seg & 2047;
            int r   = s2 >> 3, c = s2 & 7;
            const __half* g = (arr ? Al : Ah) + (size_t)(m0 + r) * 1024 + k0 + c * 8;
            uint32_t dst = bufb + arr * 32768 + SWZ128((uint32_t)(r * 128 + c * 16));
            CP16(dst, g);
        }
        // B: 1 array x 128 rows x 8 chunks = 1024 -> 4/thread
#pragma unroll
        for (int u = 0; u < 4; u++) {
            int seg = t + u * 256;
            int r = seg >> 3, c = seg & 7;
            const __half* g = Bs + (size_t)(n0 + r) * 1024 + k0 + c * 8;
            uint32_t dst = bufb + 65536 + SWZ128((uint32_t)(r * 128 + c * 16));
            CP16(dst, g);
        }
        CP_COMMIT();
    };

    float acc[4][8][4];
#pragma unroll
    for (int mf = 0; mf < 4; mf++)
#pragma unroll
        for (int nf = 0; nf < 8; nf++)
#pragma unroll
            for (int e = 0; e < 4; e++) acc[mf][nf][e] = 0.f;

    const int mat   = lane >> 3;
    const int r8    = lane & 7;
    const int aRow0 = warpM * 64 + (mat & 1) * 8 + r8;
    const int aKh   = mat >> 1;
    const int bRow0 = warpN * 64 + (mat >> 1) * 8 + r8;
    const int bKh   = mat & 1;

    stage(0);

    for (int s = 0; s < 16; s++) {
        if (s + 1 < 16) { stage(s + 1); CP_WAIT1(); }
        else            { CP_WAIT0(); }
        __syncthreads();

        const uint32_t AH = sb + (s & 1) * G_BUFSZ;
        const uint32_t AL = AH + 32768, BS = AH + 65536;

#pragma unroll
        for (int ks = 0; ks < 4; ks++) {
            uint32_t bF[4][4];
#pragma unroll
            for (int g = 0; g < 4; g++) {
                int row = bRow0 + g * 16;
                uint32_t off = (uint32_t)(row * 128 +
                               (((2 * ks + bKh) ^ (row & 7)) * 16));
                ldsm_x4(bF[g], BS + off);
            }
#pragma unroll
            for (int mf = 0; mf < 4; mf++) {
                uint32_t aH[4], aL[4];
                int row = aRow0 + mf * 16;
                uint32_t off = (uint32_t)(row * 128 +
                               (((2 * ks + aKh) ^ (row & 7)) * 16));
                ldsm_x4(aH, AH + off);
                ldsm_x4(aL, AL + off);
#pragma unroll
                for (int nf = 0; nf < 8; nf++)
                    mma_f16(acc[mf][nf], aH, &bF[nf >> 1][(nf & 1) * 2]);
#pragma unroll
                for (int nf = 0; nf < 8; nf++)
                    mma_f16(acc[mf][nf], aL, &bF[nf >> 1][(nf & 1) * 2]);
            }
        }
        __syncthreads();
    }

    const int rbase = lane >> 2;
    const int cpair = (lane & 3) * 2;
#pragma unroll
    for (int nf = 0; nf < 8; nf++) {
        int n = n0 + warpN * 64 + nf * 8 + cpair;
        float bx = __ldg(&bias[n]), by = __ldg(&bias[n + 1]);
#pragma unroll
        for (int mf = 0; mf < 4; mf++) {
            float* a = acc[mf][nf];
            int m = m0 + warpM * 64 + mf * 16 + rbase;
#pragma unroll
            for (int half_ = 0; half_ < 2; half_++) {
                int mm = m + half_ * 8;
                float vx = a[half_ * 2 + 0] + bx, vy = a[half_ * 2 + 1] + by;
                if (SPLITHEADS) {
                    int b = mm >> 11, l = mm & 2047;
                    int h = n >> 6,  d = n & 63;
                    size_t idx = (((size_t)(b * Hc + h)) * Lc + l) * Dc + d;
                    __nv_bfloat162 hv = __floats2bfloat162_rn(vx, vy);
                    __nv_bfloat162 lv = __floats2bfloat162_rn(
                        vx - __bfloat162float(hv.x), vy - __bfloat162float(hv.y));
                    *(uint32_t*)&Yh[idx] = *(uint32_t*)&hv;
                    *(uint32_t*)&Yl[idx] = *(uint32_t*)&lv;
                } else {
                    *(float2*)&Y[(size_t)mm * 1024 + n] = make_float2(vx, vy);
                }
            }
        }
    }
}

struct GemmBatch {
    const __half *Ah[3], *Al[3], *Bs[3];
    const float* bias[3];
    __nv_bfloat16 *Yh[3], *Yl[3];
};

__global__ void __launch_bounds__(256, 1) gemm_proj_kernel(GemmBatch p)
{
    extern __shared__ char smem[];
    int z = blockIdx.z;
    gemm_body<1>(p.Ah[z], p.Al[z], p.Bs[z], p.bias[z],
                 nullptr, p.Yh[z], p.Yl[z], smem);
}

__global__ void __launch_bounds__(256, 1)
gemm_out_kernel(const __half* Ah, const __half* Al, const __half* Bs,
                const float* bias, float* Y)
{
    extern __shared__ char smem[];
    gemm_body<0>(Ah, Al, Bs, bias, Y, nullptr, nullptr, smem);
}

// ============================================================================
// HMMA flash attention (bf16 3-pass, unchanged math): 256q/CTA, 32 q-rows/warp.
// Finalize writes Z as fp16 hi/lo for the fp16 out-GEMM.
// ============================================================================
#define ATT_QH 0
#define ATT_QL 32768
#define ATT_B0 65536
#define ATT_KVBUF 32768
#define ATT_MS0 131072
#define ATT_MSBUF 36864
#define ATT_SMEM 204800

__global__ void __launch_bounds__(256, 1)
attn_mma_kernel(const __nv_bfloat16* __restrict__ Qh, const __nv_bfloat16* __restrict__ Ql,
                const __nv_bfloat16* __restrict__ Kh, const __nv_bfloat16* __restrict__ Kl,
                const __nv_bfloat16* __restrict__ Vh, const __nv_bfloat16* __restrict__ Vl,
                const __nv_bfloat16* __restrict__ Mb,
                __half* __restrict__ Zh, __half* __restrict__ Zl)
{
    extern __shared__ char smem[];
    const uint32_t sb = smem_u32(smem);
    const int t  = threadIdx.x;
    const int w  = t >> 5;
    const int l  = t & 31;
    const int bh = blockIdx.y;
    const int b  = bh >> 4;
    const int h  = bh & 15;
    const int q0 = blockIdx.x * 256;

    const __nv_bfloat16* Qbh = Qh + (size_t)bh * Lc * Dc;
    const __nv_bfloat16* Qbl = Ql + (size_t)bh * Lc * Dc;
    const __nv_bfloat16* Kbh = Kh + (size_t)bh * Lc * Dc;
    const __nv_bfloat16* Kbl = Kl + (size_t)bh * Lc * Dc;
    const __nv_bfloat16* Vbh = Vh + (size_t)bh * Lc * Dc;
    const __nv_bfloat16* Vbl = Vl + (size_t)bh * Lc * Dc;
    const __nv_bfloat16* Mbb = Mb + ((size_t)b * Lc + q0) * Lc;

    const float SC = 0.125f * 1.4426950408889634f;
    const int mat = l >> 3;
    const int r8  = l & 7;
    const int gr  = l >> 2;

    const __nv_bfloat16* kvsrc[4] = {Kbh, Kbl, Vbh, Vbl};

    auto stage = [&](int s) {
        const int kt = s * 64;
        const uint32_t kvb = sb + ATT_B0 + (s & 1) * ATT_KVBUF;
        const uint32_t msb = sb + ATT_MS0 + (s & 1) * ATT_MSBUF;
#pragma unroll
        for (int u = 0; u < 8; u++) {
            int seg = t + u * 256;
            int arr = seg >> 9;
            int s2  = seg & 511;
            int r   = s2 >> 3, c = s2 & 7;
            const __nv_bfloat16* g = kvsrc[arr] + (size_t)(kt + r) * Dc + c * 8;
            uint32_t dst = kvb + arr * 8192 + SWZ128((uint32_t)(r * 128 + c * 16));
            CP16(dst, g);
        }
#pragma unroll
        for (int u = 0; u < 8; u++) {
            int seg = t + u * 256;
            int r = seg >> 3, c = seg & 7;
            const __nv_bfloat16* g = Mbb + (size_t)r * Lc + kt + c * 8;
            CP16(msb + r * 144 + c * 16, g);
        }
        CP_COMMIT();
    };

#pragma unroll
    for (int u = 0; u < 16; u++) {
        int seg = t + u * 256;
        int arr = seg >> 11;
        int s2  = seg & 2047;
        int r   = s2 >> 3, c = s2 & 7;
        const __nv_bfloat16* g = (arr ? Qbl : Qbh) + (size_t)(q0 + r) * Dc + c * 8;
        uint32_t dst = sb + (arr ? ATT_QL : ATT_QH) + SWZ128((uint32_t)(r * 128 + c * 16));
        CP16(dst, g);
    }
    stage(0);

    float accO[2][8][4];
#pragma unroll
    for (int mf = 0; mf < 2; mf++)
#pragma unroll
        for (int nf = 0; nf < 8; nf++)
#pragma unroll
            for (int e = 0; e < 4; e++) accO[mf][nf][e] = 0.f;
    float mA[2] = {-3.0e38f, -3.0e38f}, mB[2] = {-3.0e38f, -3.0e38f};
    float lA[2] = {0.f, 0.f},           lB[2] = {0.f, 0.f};

    for (int s = 0; s < 32; s++) {
        if (s + 1 < 32) { stage(s + 1); CP_WAIT1(); }
        else            { CP_WAIT0(); }
        __syncthreads();

        const uint32_t KHb = sb + ATT_B0 + (s & 1) * ATT_KVBUF;
        const uint32_t KLb = KHb + 8192, VHb = KHb + 16384, VLb = KHb + 24576;
        const uint32_t MSo = ATT_MS0 + (s & 1) * ATT_MSBUF;

        float accS[2][8][4];
#pragma unroll
        for (int mf = 0; mf < 2; mf++)
#pragma unroll
            for (int nf = 0; nf < 8; nf++)
#pragma unroll
                for (int e = 0; e < 4; e++) accS[mf][nf][e] = 0.f;

#pragma unroll
        for (int kf = 0; kf < 4; kf++) {
            uint32_t qh[2][4], ql[2][4];
#pragma unroll
            for (int mf = 0; mf < 2; mf++) {
                int row = w * 32 + mf * 16 + (mat & 1) * 8 + r8;
                int chk = kf * 2 + (mat >> 1);
                uint32_t off = (uint32_t)(row * 128 + ((chk ^ (row & 7)) * 16));
                ldsm_x4(qh[mf], sb + ATT_QH + off);
                ldsm_x4(ql[mf], sb + ATT_QL + off);
            }
#pragma unroll
            for (int g = 0; g < 4; g++) {
                uint32_t kh[4], kl[4];
                int row = g * 16 + (mat >> 1) * 8 + r8;
                int chk = kf * 2 + (mat & 1);
                uint32_t off = (uint32_t)(row * 128 + ((chk ^ (row & 7)) * 16));
                ldsm_x4(kh, KHb + off);
                ldsm_x4(kl, KLb + off);
#pragma unroll
                for (int mf = 0; mf < 2; mf++) {
                    mma_bf16(accS[mf][2 * g],     qh[mf], kh);
                    mma_bf16(accS[mf][2 * g],     qh[mf], kl);
                    mma_bf16(accS[mf][2 * g],     ql[mf], kh);
                    mma_bf16(accS[mf][2 * g + 1], qh[mf], kh + 2);
                    mma_bf16(accS[mf][2 * g + 1], qh[mf], kl + 2);
                    mma_bf16(accS[mf][2 * g + 1], ql[mf], kh + 2);
                }
            }
        }

#pragma unroll
        for (int mf = 0; mf < 2; mf++) {
            const int rw0 = w * 32 + mf * 16 + gr;
            float t0 = -3.0e38f, t1 = -3.0e38f;
#pragma unroll
            for (int nf = 0; nf < 8; nf++) {
                int colb = (nf * 8 + (l & 3) * 2) * 2;
                __nv_bfloat162 ms0 = *(__nv_bfloat162*)(smem + MSo + rw0 * 144 + colb);
                __nv_bfloat162 ms1 = *(__nv_bfloat162*)(smem + MSo + (rw0 + 8) * 144 + colb);
                accS[mf][nf][0] = fmaf(accS[mf][nf][0], SC, __bfloat162float(ms0.x));
                accS[mf][nf][1] = fmaf(accS[mf][nf][1], SC, __bfloat162float(ms0.y));
                accS[mf][nf][2] = fmaf(accS[mf][nf][2], SC, __bfloat162float(ms1.x));
                accS[mf][nf][3] = fmaf(accS[mf][nf][3], SC, __bfloat162float(ms1.y));
                t0 = fmaxf(t0, fmaxf(accS[mf][nf][0], accS[mf][nf][1]));
                t1 = fmaxf(t1, fmaxf(accS[mf][nf][2], accS[mf][nf][3]));
            }
            t0 = fmaxf(t0, __shfl_xor_sync(0xffffffffu, t0, 1));
            t0 = fmaxf(t0, __shfl_xor_sync(0xffffffffu, t0, 2));
            t1 = fmaxf(t1, __shfl_xor_sync(0xffffffffu, t1, 1));
            t1 = fmaxf(t1, __shfl_xor_sync(0xffffffffu, t1, 2));

            float mn0 = fmaxf(mA[mf], t0), mn1 = fmaxf(mB[mf], t1);
            float f0 = ex2f(mA[mf] - mn0), f1 = ex2f(mB[mf] - mn1);
            mA[mf] = mn0; mB[mf] = mn1;

            float rs0 = 0.f, rs1 = 0.f;
#pragma unroll
            for (int nf = 0; nf < 8; nf++) {
                accS[mf][nf][0] = ex2f(accS[mf][nf][0] - mA[mf]);
                accS[mf][nf][1] = ex2f(accS[mf][nf][1] - mA[mf]);
                accS[mf][nf][2] = ex2f(accS[mf][nf][2] - mB[mf]);
                accS[mf][nf][3] = ex2f(accS[mf][nf][3] - mB[mf]);
                rs0 += accS[mf][nf][0] + accS[mf][nf][1];
                rs1 += accS[mf][nf][2] + accS[mf][nf][3];
                accO[mf][nf][0] *= f0; accO[mf][nf][1] *= f0;
                accO[mf][nf][2] *= f1; accO[mf][nf][3] *= f1;
            }
            rs0 += __shfl_xor_sync(0xffffffffu, rs0, 1);
            rs0 += __shfl_xor_sync(0xffffffffu, rs0, 2);
            rs1 += __shfl_xor_sync(0xffffffffu, rs1, 1);
            rs1 += __shfl_xor_sync(0xffffffffu, rs1, 2);
            lA[mf] = lA[mf] * f0 + rs0;
            lB[mf] = lB[mf] * f1 + rs1;
        }

#pragma unroll
        for (int kf = 0; kf < 4; kf++) {
            uint32_t ah[2][4], al[2][4];
#pragma unroll
            for (int mf = 0; mf < 2; mf++) {
                const float* pA = accS[mf][2 * kf];
                const float* pB = accS[mf][2 * kf + 1];
                float ev[8] = {pA[0], pA[1], pA[2], pA[3],
                               pB[0], pB[1], pB[2], pB[3]};
#pragma unroll
                for (int i = 0; i < 4; i++) {
                    float x = ev[2 * i], y = ev[2 * i + 1];
                    __nv_bfloat16 xh = __float2bfloat16_rn(x);
                    __nv_bfloat16 yh = __float2bfloat16_rn(y);
                    ah[mf][i] = pack_bf16(x, y);
                    al[mf][i] = pack_bf16(x - __bfloat162float(xh),
                                          y - __bfloat162float(yh));
                }
            }
            int rowv = kf * 16 + (l & 15);
#pragma unroll
            for (int g = 0; g < 4; g++) {
                uint32_t vh[4], vl[4];
                int chv = g * 2 + (l >> 4);
                uint32_t off = (uint32_t)(rowv * 128 + ((chv ^ (rowv & 7)) * 16));
                ldsm_x4_t(vh, VHb + off);
                ldsm_x4_t(vl, VLb + off);
#pragma unroll
                for (int mf = 0; mf < 2; mf++) {
                    mma_bf16(accO[mf][2 * g],     ah[mf], vh);
                    mma_bf16(accO[mf][2 * g],     ah[mf], vl);
                    mma_bf16(accO[mf][2 * g],     al[mf], vh);
                    mma_bf16(accO[mf][2 * g + 1], ah[mf], vh + 2);
                    mma_bf16(accO[mf][2 * g + 1], ah[mf], vl + 2);
                    mma_bf16(accO[mf][2 * g + 1], al[mf], vh + 2);
                }
            }
        }
        __syncthreads();
    }

    // finalize: divide, split into fp16 hi/lo, write Zh/Zl
#pragma unroll
    for (int mf = 0; mf < 2; mf++) {
        float inv0 = 1.f / lA[mf], inv1 = 1.f / lB[mf];
        int qg0 = q0 + w * 32 + mf * 16 + gr;
#pragma unroll
        for (int nf = 0; nf < 8; nf++) {
            int d = nf * 8 + (l & 3) * 2;
            float x0 = accO[mf][nf][0] * inv0, y0 = accO[mf][nf][1] * inv0;
            float x1 = accO[mf][nf][2] * inv1, y1 = accO[mf][nf][3] * inv1;
            size_t i0 = ((size_t)(b * Lc + qg0)) * Cc + h * 64 + d;
            size_t i1 = ((size_t)(b * Lc + qg0 + 8)) * Cc + h * 64 + d;
            __half2 h0 = __floats2half2_rn(x0, y0);
            __half2 l0 = __floats2half2_rn(x0 - __half2float(__low2half(h0)),
                                           y0 - __half2float(__high2half(h0)));
            __half2 h1 = __floats2half2_rn(x1, y1);
            __half2 l1 = __floats2half2_rn(x1 - __half2float(__low2half(h1)),
                                           y1 - __half2float(__high2half(h1)));
            *(uint32_t*)&Zh[i0] = *(uint32_t*)&h0;
            *(uint32_t*)&Zl[i0] = *(uint32_t*)&l0;
            *(uint32_t*)&Zh[i1] = *(uint32_t*)&h1;
            *(uint32_t*)&Zl[i1] = *(uint32_t*)&l1;
        }
    }
}

// ============================================================================
// Launcher
// ============================================================================
extern "C" void kernel_launch(void* const* d_in, const int* in_sizes, int n_in,
                              void* d_out, int out_size)
{
    const float* query = (const float*)d_in[0];
    const float* key_  = (const float*)d_in[1];
    const float* value = (const float*)d_in[2];
    const int*   mask  = (const int*)  d_in[3];
    const float* WQ = (const float*)d_in[4];
    const float* bQ = (const float*)d_in[5];
    const float* WK = (const float*)d_in[6];
    const float* bK = (const float*)d_in[7];
    const float* WV = (const float*)d_in[8];
    const float* bV = (const float*)d_in[9];
    const float* WO = (const float*)d_in[10];
    const float* bO = (const float*)d_in[11];
    float* out = (float*)d_out;

    void *xqh, *xql, *xkh, *xkl, *xvh, *xvl;
    cudaGetSymbolAddress(&xqh, g_Xq_h); cudaGetSymbolAddress(&xql, g_Xq_l);
    cudaGetSymbolAddress(&xkh, g_Xk_h); cudaGetSymbolAddress(&xkl, g_Xk_l);
    cudaGetSymbolAddress(&xvh, g_Xv_h); cudaGetSymbolAddress(&xvl, g_Xv_l);
    void *qbh, *qbl, *kbh, *kbl, *vbh, *vbl, *zh, *zl, *pM;
    cudaGetSymbolAddress(&qbh, g_Qb_h); cudaGetSymbolAddress(&qbl, g_Qb_l);
    cudaGetSymbolAddress(&kbh, g_Kb_h); cudaGetSymbolAddress(&kbl, g_Kb_l);
    cudaGetSymbolAddress(&vbh, g_Vb_h); cudaGetSymbolAddress(&vbl, g_Vb_l);
    cudaGetSymbolAddress(&zh, g_Zh);    cudaGetSymbolAddress(&zl, g_Zl);
    cudaGetSymbolAddress(&pM, g_Mb);
    void *wq, *wk, *wv, *wo;
    cudaGetSymbolAddress(&wq, g_WtQ);
    cudaGetSymbolAddress(&wk, g_WtK);
    cudaGetSymbolAddress(&wv, g_WtV);
    cudaGetSymbolAddress(&wo, g_WtO);

    cudaFuncSetAttribute(attn_mma_kernel,
                         cudaFuncAttributeMaxDynamicSharedMemorySize, ATT_SMEM);
    cudaFuncSetAttribute(gemm_proj_kernel,
                         cudaFuncAttributeMaxDynamicSharedMemorySize, G_SMEM_TOTAL);
    cudaFuncSetAttribute(gemm_out_kernel,
                         cudaFuncAttributeMaxDynamicSharedMemorySize, G_SMEM_TOTAL);

    // --- Prep (fused) ---
    XSplitBatch xp;
    xp.X[0] = query; xp.X[1] = key_; xp.X[2] = value;
    xp.Xh[0] = (__half*)xqh; xp.Xl[0] = (__half*)xql;
    xp.Xh[1] = (__half*)xkh; xp.Xl[1] = (__half*)xkl;
    xp.Xh[2] = (__half*)xvh; xp.Xl[2] = (__half*)xvl;
    xsplit_kernel<<<dim3(Mc * Cc / (256 * 8), 3), 256>>>(xp);

    maskprep_kernel<<<(Bc * Lc * Lc) / (256 * 4), 256>>>(mask, (__nv_bfloat16*)pM);

    WSplitBatch wp;
    wp.W[0] = WQ; wp.W[1] = WK; wp.W[2] = WV; wp.W[3] = WO;
    wp.T[0] = (__half*)wq; wp.T[1] = (__half*)wk;
    wp.T[2] = (__half*)wv; wp.T[3] = (__half*)wo;
    wsplit_kernel<<<dim3(32, 32, 4), dim3(32, 8)>>>(wp);

    // --- Fused projection GEMMs (256m x 128n tiles) ---
    GemmBatch gp;
    gp.Ah[0] = (const __half*)xqh; gp.Al[0] = (const __half*)xql;
    gp.Ah[1] = (const __half*)xkh; gp.Al[1] = (const __half*)xkl;
    gp.Ah[2] = (const __half*)xvh; gp.Al[2] = (const __half*)xvl;
    gp.Bs[0] = (const __half*)wq;
    gp.Bs[1] = (const __half*)wk;
    gp.Bs[2] = (const __half*)wv;
    gp.bias[0] = bQ; gp.bias[1] = bK; gp.bias[2] = bV;
    gp.Yh[0] = (__nv_bfloat16*)qbh; gp.Yl[0] = (__nv_bfloat16*)qbl;
    gp.Yh[1] = (__nv_bfloat16*)kbh; gp.Yl[1] = (__nv_bfloat16*)kbl;
    gp.Yh[2] = (__nv_bfloat16*)vbh; gp.Yl[2] = (__nv_bfloat16*)vbl;
    gemm_proj_kernel<<<dim3(Cc / 128, Mc / 256, 3), 256, G_SMEM_TOTAL>>>(gp);

    dim3 attn_grid(Lc / 256, Bc * Hc);
    attn_mma_kernel<<<attn_grid, 256, ATT_SMEM>>>(
        (const __nv_bfloat16*)qbh, (const __nv_bfloat16*)qbl,
        (const __nv_bfloat16*)kbh, (const __nv_bfloat16*)kbl,
        (const __nv_bfloat16*)vbh, (const __nv_bfloat16*)vbl,
        (const __nv_bfloat16*)pM, (__half*)zh, (__half*)zl);

    gemm_out_kernel<<<dim3(Cc / 128, Mc / 256), 256, G_SMEM_TOTAL>>>(
        (const __half*)zh, (const __half*)zl, (const __half*)wo, bO, out);
}

// round 15
// speedup vs baseline: 1.3101x; 1.1450x over previous
#include <cuda_runtime.h>
#include <cuda_bf16.h>
#include <cuda_fp16.h>
#include <math.h>
#include <stdint.h>

// Problem constants
#define Bc 2
#define Lc 2048
#define Cc 1024
#define Hc 16
#define Dc 64
#define Mc (Bc*Lc)

// Scratch (device globals: allocation-free rule)
__device__ __half g_Xq_h[Mc*Cc], g_Xq_l[Mc*Cc];
__device__ __half g_Xk_h[Mc*Cc], g_Xk_l[Mc*Cc];
__device__ __half g_Xv_h[Mc*Cc], g_Xv_l[Mc*Cc];
__device__ __half g_Qb_h[Bc*Hc*Lc*Dc], g_Qb_l[Bc*Hc*Lc*Dc];   // fp16 hi/lo
__device__ __half g_Kb_h[Bc*Hc*Lc*Dc], g_Kb_l[Bc*Hc*Lc*Dc];   // attn uses hi only
__device__ __half g_Vb_h[Bc*Hc*Lc*Dc], g_Vb_l[Bc*Hc*Lc*Dc];   // attn uses hi only
__device__ __half g_Zh[Bc*Lc*Cc], g_Zl[Bc*Lc*Cc];
__device__ __nv_bfloat16 g_Mb[Bc*Lc*Lc];

// Single fp16 weights, transposed [N][K]
__device__ __half g_WtQ[Cc*Cc];
__device__ __half g_WtK[Cc*Cc];
__device__ __half g_WtV[Cc*Cc];
__device__ __half g_WtO[Cc*Cc];

// ============================================================================
// Helpers
// ============================================================================
__device__ __forceinline__ uint32_t smem_u32(const void* p) {
    uint32_t a;
    asm("{ .reg .u64 t; cvta.to.shared.u64 t, %1; cvt.u32.u64 %0, t; }"
        : "=r"(a) : "l"(p));
    return a;
}
#define SWZ128(off) ((off) ^ (((off) >> 3) & 0x70))

#define CP16(dst, src) \
    asm volatile("cp.async.cg.shared.global [%0], [%1], 16;" \
                 :: "r"(dst), "l"(src) : "memory")
#define CP_COMMIT() asm volatile("cp.async.commit_group;" ::: "memory")
#define CP_WAIT1()  asm volatile("cp.async.wait_group 1;" ::: "memory")
#define CP_WAIT0()  asm volatile("cp.async.wait_group 0;" ::: "memory")

__device__ __forceinline__ void ldsm_x4(uint32_t* r, uint32_t addr) {
    asm volatile("ldmatrix.sync.aligned.m8n8.x4.shared.b16 {%0,%1,%2,%3}, [%4];"
                 : "=r"(r[0]), "=r"(r[1]), "=r"(r[2]), "=r"(r[3]) : "r"(addr));
}
__device__ __forceinline__ void ldsm_x4_t(uint32_t* r, uint32_t addr) {
    asm volatile("ldmatrix.sync.aligned.m8n8.x4.trans.shared.b16 {%0,%1,%2,%3}, [%4];"
                 : "=r"(r[0]), "=r"(r[1]), "=r"(r[2]), "=r"(r[3]) : "r"(addr));
}
__device__ __forceinline__ void mma_f16(float* c, const uint32_t* a,
                                        const uint32_t* b) {
    asm volatile(
        "mma.sync.aligned.m16n8k16.row.col.f32.f16.f16.f32 "
        "{%0,%1,%2,%3}, {%4,%5,%6,%7}, {%8,%9}, {%0,%1,%2,%3};"
        : "+f"(c[0]), "+f"(c[1]), "+f"(c[2]), "+f"(c[3])
        : "r"(a[0]), "r"(a[1]), "r"(a[2]), "r"(a[3]), "r"(b[0]), "r"(b[1]));
}
__device__ __forceinline__ uint32_t pack_h2(float x, float y) {
    __half2 v = __floats2half2_rn(x, y);
    return *(uint32_t*)&v;
}
__device__ __forceinline__ float ex2f(float x) {
    float y;
    asm("ex2.approx.f32 %0, %1;" : "=f"(y) : "f"(x));
    return y;
}

// ============================================================================
// Prep kernels
// ============================================================================
struct XSplitBatch {
    const float* X[3];
    __half *Xh[3], *Xl[3];
};
__global__ void xsplit_kernel(XSplitBatch p)
{
    int z = blockIdx.y;
    size_t i = ((size_t)blockIdx.x * 256 + threadIdx.x) * 8;
    const float4* src = (const float4*)&p.X[z][i];
    float4 x0 = src[0], x1 = src[1];
    float xs[8] = {x0.x, x0.y, x0.z, x0.w, x1.x, x1.y, x1.z, x1.w};
    __half hh[8], ll[8];
#pragma unroll
    for (int e = 0; e < 8; e++) {
        hh[e] = __float2half_rn(xs[e]);
        ll[e] = __float2half_rn(xs[e] - __half2float(hh[e]));
    }
    *(uint4*)&p.Xh[z][i] = *(uint4*)hh;
    *(uint4*)&p.Xl[z][i] = *(uint4*)ll;
}

struct WSplitBatch {
    const float* W[4];
    __half* T[4];
};
__global__ void wsplit_kernel(WSplitBatch p)
{
    __shared__ float tile[32][33];
    int z = blockIdx.z;
    int n0 = blockIdx.x * 32, k0 = blockIdx.y * 32;
    int tx = threadIdx.x, ty = threadIdx.y;
#pragma unroll
    for (int i = 0; i < 32; i += 8)
        tile[ty + i][tx] = p.W[z][(size_t)(k0 + ty + i) * Cc + n0 + tx];
    __syncthreads();
#pragma unroll
    for (int i = 0; i < 32; i += 8) {
        size_t idx = (size_t)(n0 + ty + i) * Cc + k0 + tx;
        p.T[z][idx] = __float2half_rn(tile[tx][ty + i]);
    }
}

__global__ void maskprep_kernel(const int* __restrict__ m,
                                __nv_bfloat16* __restrict__ out)
{
    int i = (blockIdx.x * 256 + threadIdx.x) * 4;
    int4 v = *(const int4*)&m[i];
    __nv_bfloat162 a, b2;
    a.x  = __float2bfloat16_rn((float)(v.x - 1) * 2.0e9f);
    a.y  = __float2bfloat16_rn((float)(v.y - 1) * 2.0e9f);
    b2.x = __float2bfloat16_rn((float)(v.z - 1) * 2.0e9f);
    b2.y = __float2bfloat16_rn((float)(v.w - 1) * 2.0e9f);
    uint2 o; o.x = *(uint32_t*)&a; o.y = *(uint32_t*)&b2;
    *(uint2*)&out[i] = o;
}

// ============================================================================
// HMMA GEMM (fp16 2-pass, unchanged from R14): CTA 256x128, warp 64x64.
// SPLITHEADS epilogue now writes fp16 hi/lo.
// ============================================================================
#define G_BUFSZ 81920
#define G_SMEM_TOTAL (2*G_BUFSZ)

template<int SPLITHEADS>
__device__ __forceinline__ void gemm_body(
    const __half* __restrict__ Ah, const __half* __restrict__ Al,
    const __half* __restrict__ Bs,
    const float* __restrict__ bias, float* __restrict__ Y,
    __half* __restrict__ Yh, __half* __restrict__ Yl,
    char* smem)
{
    const uint32_t sb = smem_u32(smem);
    const int t     = threadIdx.x;
    const int wid   = t >> 5;
    const int lane  = t & 31;
    const int warpM = wid & 3;
    const int warpN = wid >> 2;
    const int n0    = blockIdx.x * 128;
    const int m0    = blockIdx.y * 256;

    auto stage = [&](int s) {
        const int k0 = s * 64;
        const uint32_t bufb = sb + (s & 1) * G_BUFSZ;
#pragma unroll
        for (int u = 0; u < 16; u++) {
            int seg = t + u * 256;
            int arr = seg >> 11;
            int s2  = seg & 2047;
            int r   = s2 >> 3, c = s2 & 7;
            const __half* g = (arr ? Al : Ah) + (size_t)(m0 + r) * 1024 + k0 + c * 8;
            uint32_t dst = bufb + arr * 32768 + SWZ128((uint32_t)(r * 128 + c * 16));
            CP16(dst, g);
        }
#pragma unroll
        for (int u = 0; u < 4; u++) {
            int seg = t + u * 256;
            int r = seg >> 3, c = seg & 7;
            const __half* g = Bs + (size_t)(n0 + r) * 1024 + k0 + c * 8;
            uint32_t dst = bufb + 65536 + SWZ128((uint32_t)(r * 128 + c * 16));
            CP16(dst, g);
        }
        CP_COMMIT();
    };

    float acc[4][8][4];
#pragma unroll
    for (int mf = 0; mf < 4; mf++)
#pragma unroll
        for (int nf = 0; nf < 8; nf++)
#pragma unroll
            for (int e = 0; e < 4; e++) acc[mf][nf][e] = 0.f;

    const int mat   = lane >> 3;
    const int r8    = lane & 7;
    const int aRow0 = warpM * 64 + (mat & 1) * 8 + r8;
    const int aKh   = mat >> 1;
    const int bRow0 = warpN * 64 + (mat >> 1) * 8 + r8;
    const int bKh   = mat & 1;

    stage(0);

    for (int s = 0; s < 16; s++) {
        if (s + 1 < 16) { stage(s + 1); CP_WAIT1(); }
        else            { CP_WAIT0(); }
        __syncthreads();

        const uint32_t AH = sb + (s & 1) * G_BUFSZ;
        const uint32_t AL = AH + 32768, BS = AH + 65536;

#pragma unroll
        for (int ks = 0; ks < 4; ks++) {
            uint32_t bF[4][4];
#pragma unroll
            for (int g = 0; g < 4; g++) {
                int row = bRow0 + g * 16;
                uint32_t off = (uint32_t)(row * 128 +
                               (((2 * ks + bKh) ^ (row & 7)) * 16));
                ldsm_x4(bF[g], BS + off);
            }
#pragma unroll
            for (int mf = 0; mf < 4; mf++) {
                uint32_t aH[4], aL[4];
                int row = aRow0 + mf * 16;
                uint32_t off = (uint32_t)(row * 128 +
                               (((2 * ks + aKh) ^ (row & 7)) * 16));
                ldsm_x4(aH, AH + off);
                ldsm_x4(aL, AL + off);
#pragma unroll
                for (int nf = 0; nf < 8; nf++)
                    mma_f16(acc[mf][nf], aH, &bF[nf >> 1][(nf & 1) * 2]);
#pragma unroll
                for (int nf = 0; nf < 8; nf++)
                    mma_f16(acc[mf][nf], aL, &bF[nf >> 1][(nf & 1) * 2]);
            }
        }
        __syncthreads();
    }

    const int rbase = lane >> 2;
    const int cpair = (lane & 3) * 2;
#pragma unroll
    for (int nf = 0; nf < 8; nf++) {
        int n = n0 + warpN * 64 + nf * 8 + cpair;
        float bx = __ldg(&bias[n]), by = __ldg(&bias[n + 1]);
#pragma unroll
        for (int mf = 0; mf < 4; mf++) {
            float* a = acc[mf][nf];
            int m = m0 + warpM * 64 + mf * 16 + rbase;
#pragma unroll
            for (int half_ = 0; half_ < 2; half_++) {
                int mm = m + half_ * 8;
                float vx = a[half_ * 2 + 0] + bx, vy = a[half_ * 2 + 1] + by;
                if (SPLITHEADS) {
                    int b = mm >> 11, l = mm & 2047;
                    int h = n >> 6,  d = n & 63;
                    size_t idx = (((size_t)(b * Hc + h)) * Lc + l) * Dc + d;
                    __half2 hv = __floats2half2_rn(vx, vy);
                    __half2 lv = __floats2half2_rn(
                        vx - __half2float(__low2half(hv)),
                        vy - __half2float(__high2half(hv)));
                    *(uint32_t*)&Yh[idx] = *(uint32_t*)&hv;
                    *(uint32_t*)&Yl[idx] = *(uint32_t*)&lv;
                } else {
                    *(float2*)&Y[(size_t)mm * 1024 + n] = make_float2(vx, vy);
                }
            }
        }
    }
}

struct GemmBatch {
    const __half *Ah[3], *Al[3], *Bs[3];
    const float* bias[3];
    __half *Yh[3], *Yl[3];
};

__global__ void __launch_bounds__(256, 1) gemm_proj_kernel(GemmBatch p)
{
    extern __shared__ char smem[];
    int z = blockIdx.z;
    gemm_body<1>(p.Ah[z], p.Al[z], p.Bs[z], p.bias[z],
                 nullptr, p.Yh[z], p.Yl[z], smem);
}

__global__ void __launch_bounds__(256, 1)
gemm_out_kernel(const __half* Ah, const __half* Al, const __half* Bs,
                const float* bias, float* Y)
{
    extern __shared__ char smem[];
    gemm_body<0>(Ah, Al, Bs, bias, Y, nullptr, nullptr, smem);
}

// ============================================================================
// HMMA flash attention v7 (fp16 2-pass): Q fp16 hi/lo, K/V single fp16.
// 256q/CTA, 32 q-rows/warp. S: qh*k + ql*k. PV: ph*v + pl*v.
// K/V staging halved vs R14.
// ============================================================================
#define ATT_QH 0
#define ATT_QL 32768
#define ATT_B0 65536             // 2 KV buffers of 16384 (K 8K | V 8K)
#define ATT_KVBUF 16384
#define ATT_MS0 98304            // 2 mask buffers of 36864
#define ATT_MSBUF 36864
#define ATT_SMEM 172032

__global__ void __launch_bounds__(256, 1)
attn_mma_kernel(const __half* __restrict__ Qh, const __half* __restrict__ Ql,
                const __half* __restrict__ Kv, const __half* __restrict__ Vv,
                const __nv_bfloat16* __restrict__ Mb,
                __half* __restrict__ Zh, __half* __restrict__ Zl)
{
    extern __shared__ char smem[];
    const uint32_t sb = smem_u32(smem);
    const int t  = threadIdx.x;
    const int w  = t >> 5;
    const int l  = t & 31;
    const int bh = blockIdx.y;
    const int b  = bh >> 4;
    const int h  = bh & 15;
    const int q0 = blockIdx.x * 256;

    const __half* Qbh = Qh + (size_t)bh * Lc * Dc;
    const __half* Qbl = Ql + (size_t)bh * Lc * Dc;
    const __half* Kb  = Kv + (size_t)bh * Lc * Dc;
    const __half* Vb  = Vv + (size_t)bh * Lc * Dc;
    const __nv_bfloat16* Mbb = Mb + ((size_t)b * Lc + q0) * Lc;

    const float SC = 0.125f * 1.4426950408889634f;
    const int mat = l >> 3;
    const int r8  = l & 7;
    const int gr  = l >> 2;

    auto stage = [&](int s) {
        const int kt = s * 64;
        const uint32_t kvb = sb + ATT_B0 + (s & 1) * ATT_KVBUF;
        const uint32_t msb = sb + ATT_MS0 + (s & 1) * ATT_MSBUF;
        // K,V: 2 arrays x 64 rows x 8 chunks = 1024 -> 4/thread
#pragma unroll
        for (int u = 0; u < 4; u++) {
            int seg = t + u * 256;
            int arr = seg >> 9;
            int s2  = seg & 511;
            int r   = s2 >> 3, c = s2 & 7;
            const __half* g = (arr ? Vb : Kb) + (size_t)(kt + r) * Dc + c * 8;
            uint32_t dst = kvb + arr * 8192 + SWZ128((uint32_t)(r * 128 + c * 16));
            CP16(dst, g);
        }
        // mask: 256 rows x 8 chunks = 2048 -> 8/thread
#pragma unroll
        for (int u = 0; u < 8; u++) {
            int seg = t + u * 256;
            int r = seg >> 3, c = seg & 7;
            const __nv_bfloat16* g = Mbb + (size_t)r * Lc + kt + c * 8;
            CP16(msb + r * 144 + c * 16, g);
        }
        CP_COMMIT();
    };

    // Prologue: Q hi/lo
#pragma unroll
    for (int u = 0; u < 16; u++) {
        int seg = t + u * 256;
        int arr = seg >> 11;
        int s2  = seg & 2047;
        int r   = s2 >> 3, c = s2 & 7;
        const __half* g = (arr ? Qbl : Qbh) + (size_t)(q0 + r) * Dc + c * 8;
        uint32_t dst = sb + (arr ? ATT_QL : ATT_QH) + SWZ128((uint32_t)(r * 128 + c * 16));
        CP16(dst, g);
    }
    stage(0);

    float accO[2][8][4];
#pragma unroll
    for (int mf = 0; mf < 2; mf++)
#pragma unroll
        for (int nf = 0; nf < 8; nf++)
#pragma unroll
            for (int e = 0; e < 4; e++) accO[mf][nf][e] = 0.f;
    float mA[2] = {-3.0e38f, -3.0e38f}, mB[2] = {-3.0e38f, -3.0e38f};
    float lA[2] = {0.f, 0.f},           lB[2] = {0.f, 0.f};

    for (int s = 0; s < 32; s++) {
        if (s + 1 < 32) { stage(s + 1); CP_WAIT1(); }
        else            { CP_WAIT0(); }
        __syncthreads();

        const uint32_t KHb = sb + ATT_B0 + (s & 1) * ATT_KVBUF;
        const uint32_t VHb = KHb + 8192;
        const uint32_t MSo = ATT_MS0 + (s & 1) * ATT_MSBUF;

        // --- S = Q K^T (2-pass: qh*k + ql*k) ---
        float accS[2][8][4];
#pragma unroll
        for (int mf = 0; mf < 2; mf++)
#pragma unroll
            for (int nf = 0; nf < 8; nf++)
#pragma unroll
                for (int e = 0; e < 4; e++) accS[mf][nf][e] = 0.f;

#pragma unroll
        for (int kf = 0; kf < 4; kf++) {
            uint32_t qh[2][4], ql[2][4];
#pragma unroll
            for (int mf = 0; mf < 2; mf++) {
                int row = w * 32 + mf * 16 + (mat & 1) * 8 + r8;
                int chk = kf * 2 + (mat >> 1);
                uint32_t off = (uint32_t)(row * 128 + ((chk ^ (row & 7)) * 16));
                ldsm_x4(qh[mf], sb + ATT_QH + off);
                ldsm_x4(ql[mf], sb + ATT_QL + off);
            }
#pragma unroll
            for (int g = 0; g < 4; g++) {
                uint32_t kh[4];
                int row = g * 16 + (mat >> 1) * 8 + r8;
                int chk = kf * 2 + (mat & 1);
                uint32_t off = (uint32_t)(row * 128 + ((chk ^ (row & 7)) * 16));
                ldsm_x4(kh, KHb + off);
#pragma unroll
                for (int mf = 0; mf < 2; mf++) {
                    mma_f16(accS[mf][2 * g],     qh[mf], kh);
                    mma_f16(accS[mf][2 * g],     ql[mf], kh);
                    mma_f16(accS[mf][2 * g + 1], qh[mf], kh + 2);
                    mma_f16(accS[mf][2 * g + 1], ql[mf], kh + 2);
                }
            }
        }

        // --- softmax (fp32, log2 domain; MUFU ex2) ---
#pragma unroll
        for (int mf = 0; mf < 2; mf++) {
            const int rw0 = w * 32 + mf * 16 + gr;
            float t0 = -3.0e38f, t1 = -3.0e38f;
#pragma unroll
            for (int nf = 0; nf < 8; nf++) {
                int colb = (nf * 8 + (l & 3) * 2) * 2;
                __nv_bfloat162 ms0 = *(__nv_bfloat162*)(smem + MSo + rw0 * 144 + colb);
                __nv_bfloat162 ms1 = *(__nv_bfloat162*)(smem + MSo + (rw0 + 8) * 144 + colb);
                accS[mf][nf][0] = fmaf(accS[mf][nf][0], SC, __bfloat162float(ms0.x));
                accS[mf][nf][1] = fmaf(accS[mf][nf][1], SC, __bfloat162float(ms0.y));
                accS[mf][nf][2] = fmaf(accS[mf][nf][2], SC, __bfloat162float(ms1.x));
                accS[mf][nf][3] = fmaf(accS[mf][nf][3], SC, __bfloat162float(ms1.y));
                t0 = fmaxf(t0, fmaxf(accS[mf][nf][0], accS[mf][nf][1]));
                t1 = fmaxf(t1, fmaxf(accS[mf][nf][2], accS[mf][nf][3]));
            }
            t0 = fmaxf(t0, __shfl_xor_sync(0xffffffffu, t0, 1));
            t0 = fmaxf(t0, __shfl_xor_sync(0xffffffffu, t0, 2));
            t1 = fmaxf(t1, __shfl_xor_sync(0xffffffffu, t1, 1));
            t1 = fmaxf(t1, __shfl_xor_sync(0xffffffffu, t1, 2));

            float mn0 = fmaxf(mA[mf], t0), mn1 = fmaxf(mB[mf], t1);
            float f0 = ex2f(mA[mf] - mn0), f1 = ex2f(mB[mf] - mn1);
            mA[mf] = mn0; mB[mf] = mn1;

            float rs0 = 0.f, rs1 = 0.f;
#pragma unroll
            for (int nf = 0; nf < 8; nf++) {
                accS[mf][nf][0] = ex2f(accS[mf][nf][0] - mA[mf]);
                accS[mf][nf][1] = ex2f(accS[mf][nf][1] - mA[mf]);
                accS[mf][nf][2] = ex2f(accS[mf][nf][2] - mB[mf]);
                accS[mf][nf][3] = ex2f(accS[mf][nf][3] - mB[mf]);
                rs0 += accS[mf][nf][0] + accS[mf][nf][1];
                rs1 += accS[mf][nf][2] + accS[mf][nf][3];
                accO[mf][nf][0] *= f0; accO[mf][nf][1] *= f0;
                accO[mf][nf][2] *= f1; accO[mf][nf][3] *= f1;
            }
            rs0 += __shfl_xor_sync(0xffffffffu, rs0, 1);
            rs0 += __shfl_xor_sync(0xffffffffu, rs0, 2);
            rs1 += __shfl_xor_sync(0xffffffffu, rs1, 1);
            rs1 += __shfl_xor_sync(0xffffffffu, rs1, 2);
            lA[mf] = lA[mf] * f0 + rs0;
            lB[mf] = lB[mf] * f1 + rs1;
        }

        // --- O += P @ V (2-pass: ph*v + pl*v; P fp16 hi/lo from registers) ---
#pragma unroll
        for (int kf = 0; kf < 4; kf++) {
            uint32_t ah[2][4], al[2][4];
#pragma unroll
            for (int mf = 0; mf < 2; mf++) {
                const float* pA = accS[mf][2 * kf];
                const float* pB = accS[mf][2 * kf + 1];
                float ev[8] = {pA[0], pA[1], pA[2], pA[3],
                               pB[0], pB[1], pB[2], pB[3]};
#pragma unroll
                for (int i = 0; i < 4; i++) {
                    float x = ev[2 * i], y = ev[2 * i + 1];
                    __half xh = __float2half_rn(x);
                    __half yh = __float2half_rn(y);
                    ah[mf][i] = pack_h2(x, y);
                    al[mf][i] = pack_h2(x - __half2float(xh),
                                        y - __half2float(yh));
                }
            }
            int rowv = kf * 16 + (l & 15);
#pragma unroll
            for (int g = 0; g < 4; g++) {
                uint32_t vh[4];
                int chv = g * 2 + (l >> 4);
                uint32_t off = (uint32_t)(rowv * 128 + ((chv ^ (rowv & 7)) * 16));
                ldsm_x4_t(vh, VHb + off);
#pragma unroll
                for (int mf = 0; mf < 2; mf++) {
                    mma_f16(accO[mf][2 * g],     ah[mf], vh);
                    mma_f16(accO[mf][2 * g],     al[mf], vh);
                    mma_f16(accO[mf][2 * g + 1], ah[mf], vh + 2);
                    mma_f16(accO[mf][2 * g + 1], al[mf], vh + 2);
                }
            }
        }
        __syncthreads();
    }

    // finalize: divide, split fp16 hi/lo, write Zh/Zl
#pragma unroll
    for (int mf = 0; mf < 2; mf++) {
        float inv0 = 1.f / lA[mf], inv1 = 1.f / lB[mf];
        int qg0 = q0 + w * 32 + mf * 16 + gr;
#pragma unroll
        for (int nf = 0; nf < 8; nf++) {
            int d = nf * 8 + (l & 3) * 2;
            float x0 = accO[mf][nf][0] * inv0, y0 = accO[mf][nf][1] * inv0;
            float x1 = accO[mf][nf][2] * inv1, y1 = accO[mf][nf][3] * inv1;
            size_t i0 = ((size_t)(b * Lc + qg0)) * Cc + h * 64 + d;
            size_t i1 = ((size_t)(b * Lc + qg0 + 8)) * Cc + h * 64 + d;
            __half2 h0 = __floats2half2_rn(x0, y0);
            __half2 l0 = __floats2half2_rn(x0 - __half2float(__low2half(h0)),
                                           y0 - __half2float(__high2half(h0)));
            __half2 h1 = __floats2half2_rn(x1, y1);
            __half2 l1 = __floats2half2_rn(x1 - __half2float(__low2half(h1)),
                                           y1 - __half2float(__high2half(h1)));
            *(uint32_t*)&Zh[i0] = *(uint32_t*)&h0;
            *(uint32_t*)&Zl[i0] = *(uint32_t*)&l0;
            *(uint32_t*)&Zh[i1] = *(uint32_t*)&h1;
            *(uint32_t*)&Zl[i1] = *(uint32_t*)&l1;
        }
    }
}

// ============================================================================
// Launcher
// ============================================================================
extern "C" void kernel_launch(void* const* d_in, const int* in_sizes, int n_in,
                              void* d_out, int out_size)
{
    const float* query = (const float*)d_in[0];
    const float* key_  = (const float*)d_in[1];
    const float* value = (const float*)d_in[2];
    const int*   mask  = (const int*)  d_in[3];
    const float* WQ = (const float*)d_in[4];
    const float* bQ = (const float*)d_in[5];
    const float* WK = (const float*)d_in[6];
    const float* bK = (const float*)d_in[7];
    const float* WV = (const float*)d_in[8];
    const float* bV = (const float*)d_in[9];
    const float* WO = (const float*)d_in[10];
    const float* bO = (const float*)d_in[11];
    float* out = (float*)d_out;

    void *xqh, *xql, *xkh, *xkl, *xvh, *xvl;
    cudaGetSymbolAddress(&xqh, g_Xq_h); cudaGetSymbolAddress(&xql, g_Xq_l);
    cudaGetSymbolAddress(&xkh, g_Xk_h); cudaGetSymbolAddress(&xkl, g_Xk_l);
    cudaGetSymbolAddress(&xvh, g_Xv_h); cudaGetSymbolAddress(&xvl, g_Xv_l);
    void *qbh, *qbl, *kbh, *kbl, *vbh, *vbl, *zh, *zl, *pM;
    cudaGetSymbolAddress(&qbh, g_Qb_h); cudaGetSymbolAddress(&qbl, g_Qb_l);
    cudaGetSymbolAddress(&kbh, g_Kb_h); cudaGetSymbolAddress(&kbl, g_Kb_l);
    cudaGetSymbolAddress(&vbh, g_Vb_h); cudaGetSymbolAddress(&vbl, g_Vb_l);
    cudaGetSymbolAddress(&zh, g_Zh);    cudaGetSymbolAddress(&zl, g_Zl);
    cudaGetSymbolAddress(&pM, g_Mb);
    void *wq, *wk, *wv, *wo;
    cudaGetSymbolAddress(&wq, g_WtQ);
    cudaGetSymbolAddress(&wk, g_WtK);
    cudaGetSymbolAddress(&wv, g_WtV);
    cudaGetSymbolAddress(&wo, g_WtO);

    cudaFuncSetAttribute(attn_mma_kernel,
                         cudaFuncAttributeMaxDynamicSharedMemorySize, ATT_SMEM);
    cudaFuncSetAttribute(gemm_proj_kernel,
                         cudaFuncAttributeMaxDynamicSharedMemorySize, G_SMEM_TOTAL);
    cudaFuncSetAttribute(gemm_out_kernel,
                         cudaFuncAttributeMaxDynamicSharedMemorySize, G_SMEM_TOTAL);

    // --- Prep (fused) ---
    XSplitBatch xp;
    xp.X[0] = query; xp.X[1] = key_; xp.X[2] = value;
    xp.Xh[0] = (__half*)xqh; xp.Xl[0] = (__half*)xql;
    xp.Xh[1] = (__half*)xkh; xp.Xl[1] = (__half*)xkl;
    xp.Xh[2] = (__half*)xvh; xp.Xl[2] = (__half*)xvl;
    xsplit_kernel<<<dim3(Mc * Cc / (256 * 8), 3), 256>>>(xp);

    maskprep_kernel<<<(Bc * Lc * Lc) / (256 * 4), 256>>>(mask, (__nv_bfloat16*)pM);

    WSplitBatch wp;
    wp.W[0] = WQ; wp.W[1] = WK; wp.W[2] = WV; wp.W[3] = WO;
    wp.T[0] = (__half*)wq; wp.T[1] = (__half*)wk;
    wp.T[2] = (__half*)wv; wp.T[3] = (__half*)wo;
    wsplit_kernel<<<dim3(32, 32, 4), dim3(32, 8)>>>(wp);

    // --- Fused projection GEMMs ---
    GemmBatch gp;
    gp.Ah[0] = (const __half*)xqh; gp.Al[0] = (const __half*)xql;
    gp.Ah[1] = (const __half*)xkh; gp.Al[1] = (const __half*)xkl;
    gp.Ah[2] = (const __half*)xvh; gp.Al[2] = (const __half*)xvl;
    gp.Bs[0] = (const __half*)wq;
    gp.Bs[1] = (const __half*)wk;
    gp.Bs[2] = (const __half*)wv;
    gp.bias[0] = bQ; gp.bias[1] = bK; gp.bias[2] = bV;
    gp.Yh[0] = (__half*)qbh; gp.Yl[0] = (__half*)qbl;
    gp.Yh[1] = (__half*)kbh; gp.Yl[1] = (__half*)kbl;
    gp.Yh[2] = (__half*)vbh; gp.Yl[2] = (__half*)vbl;
    gemm_proj_kernel<<<dim3(Cc / 128, Mc / 256, 3), 256, G_SMEM_TOTAL>>>(gp);

    dim3 attn_grid(Lc / 256, Bc * Hc);
    attn_mma_kernel<<<attn_grid, 256, ATT_SMEM>>>(
        (const __half*)qbh, (const __half*)qbl,
        (const __half*)kbh, (const __half*)vbh,
        (const __nv_bfloat16*)pM, (__half*)zh, (__half*)zl);

    gemm_out_kernel<<<dim3(Cc / 128, Mc / 256), 256, G_SMEM_TOTAL>>>(
        (const __half*)zh, (const __half*)zl, (const __half*)wo, bO, out);
}

// round 16
// speedup vs baseline: 1.4994x; 1.1445x over previous
#include <cuda_runtime.h>
#include <cuda_bf16.h>
#include <cuda_fp16.h>
#include <math.h>
#include <stdint.h>

// Problem constants
#define Bc 2
#define Lc 2048
#define Cc 1024
#define Hc 16
#define Dc 64
#define Mc (Bc*Lc)

// Scratch (device globals: allocation-free rule)
__device__ __half g_Xq_h[Mc*Cc], g_Xq_l[Mc*Cc];
__device__ __half g_Xk_h[Mc*Cc], g_Xk_l[Mc*Cc];
__device__ __half g_Xv_h[Mc*Cc], g_Xv_l[Mc*Cc];
__device__ __half g_Qb_h[Bc*Hc*Lc*Dc], g_Qb_l[Bc*Hc*Lc*Dc];
__device__ __half g_Kb_h[Bc*Hc*Lc*Dc], g_Kb_l[Bc*Hc*Lc*Dc];
__device__ __half g_Vb_h[Bc*Hc*Lc*Dc], g_Vb_l[Bc*Hc*Lc*Dc];
__device__ __half g_Z[Bc*Lc*Cc];              // single fp16 Z
__device__ __nv_bfloat16 g_Mb[Bc*Lc*Lc];

// Single fp16 weights, transposed [N][K]
__device__ __half g_WtQ[Cc*Cc];
__device__ __half g_WtK[Cc*Cc];
__device__ __half g_WtV[Cc*Cc];
__device__ __half g_WtO[Cc*Cc];

// ============================================================================
// Helpers
// ============================================================================
__device__ __forceinline__ uint32_t smem_u32(const void* p) {
    uint32_t a;
    asm("{ .reg .u64 t; cvta.to.shared.u64 t, %1; cvt.u32.u64 %0, t; }"
        : "=r"(a) : "l"(p));
    return a;
}
#define SWZ128(off) ((off) ^ (((off) >> 3) & 0x70))

#define CP16(dst, src) \
    asm volatile("cp.async.cg.shared.global [%0], [%1], 16;" \
                 :: "r"(dst), "l"(src) : "memory")
#define CP_COMMIT() asm volatile("cp.async.commit_group;" ::: "memory")
#define CP_WAIT1()  asm volatile("cp.async.wait_group 1;" ::: "memory")
#define CP_WAIT0()  asm volatile("cp.async.wait_group 0;" ::: "memory")

__device__ __forceinline__ void ldsm_x4(uint32_t* r, uint32_t addr) {
    asm volatile("ldmatrix.sync.aligned.m8n8.x4.shared.b16 {%0,%1,%2,%3}, [%4];"
                 : "=r"(r[0]), "=r"(r[1]), "=r"(r[2]), "=r"(r[3]) : "r"(addr));
}
__device__ __forceinline__ void ldsm_x4_t(uint32_t* r, uint32_t addr) {
    asm volatile("ldmatrix.sync.aligned.m8n8.x4.trans.shared.b16 {%0,%1,%2,%3}, [%4];"
                 : "=r"(r[0]), "=r"(r[1]), "=r"(r[2]), "=r"(r[3]) : "r"(addr));
}
__device__ __forceinline__ void mma_f16(float* c, const uint32_t* a,
                                        const uint32_t* b) {
    asm volatile(
        "mma.sync.aligned.m16n8k16.row.col.f32.f16.f16.f32 "
        "{%0,%1,%2,%3}, {%4,%5,%6,%7}, {%8,%9}, {%0,%1,%2,%3};"
        : "+f"(c[0]), "+f"(c[1]), "+f"(c[2]), "+f"(c[3])
        : "r"(a[0]), "r"(a[1]), "r"(a[2]), "r"(a[3]), "r"(b[0]), "r"(b[1]));
}
__device__ __forceinline__ uint32_t pack_h2(float x, float y) {
    __half2 v = __floats2half2_rn(x, y);
    return *(uint32_t*)&v;
}
__device__ __forceinline__ float ex2f(float x) {
    float y;
    asm("ex2.approx.f32 %0, %1;" : "=f"(y) : "f"(x));
    return y;
}

// ============================================================================
// Prep kernels
// ============================================================================
struct XSplitBatch {
    const float* X[3];
    __half *Xh[3], *Xl[3];
};
__global__ void xsplit_kernel(XSplitBatch p)
{
    int z = blockIdx.y;
    size_t i = ((size_t)blockIdx.x * 256 + threadIdx.x) * 8;
    const float4* src = (const float4*)&p.X[z][i];
    float4 x0 = src[0], x1 = src[1];
    float xs[8] = {x0.x, x0.y, x0.z, x0.w, x1.x, x1.y, x1.z, x1.w};
    __half hh[8], ll[8];
#pragma unroll
    for (int e = 0; e < 8; e++) {
        hh[e] = __float2half_rn(xs[e]);
        ll[e] = __float2half_rn(xs[e] - __half2float(hh[e]));
    }
    *(uint4*)&p.Xh[z][i] = *(uint4*)hh;
    *(uint4*)&p.Xl[z][i] = *(uint4*)ll;
}

struct WSplitBatch {
    const float* W[4];
    __half* T[4];
};
__global__ void wsplit_kernel(WSplitBatch p)
{
    __shared__ float tile[32][33];
    int z = blockIdx.z;
    int n0 = blockIdx.x * 32, k0 = blockIdx.y * 32;
    int tx = threadIdx.x, ty = threadIdx.y;
#pragma unroll
    for (int i = 0; i < 32; i += 8)
        tile[ty + i][tx] = p.W[z][(size_t)(k0 + ty + i) * Cc + n0 + tx];
    __syncthreads();
#pragma unroll
    for (int i = 0; i < 32; i += 8) {
        size_t idx = (size_t)(n0 + ty + i) * Cc + k0 + tx;
        p.T[z][idx] = __float2half_rn(tile[tx][ty + i]);
    }
}

__global__ void maskprep_kernel(const int* __restrict__ m,
                                __nv_bfloat16* __restrict__ out)
{
    int i = (blockIdx.x * 256 + threadIdx.x) * 4;
    int4 v = *(const int4*)&m[i];
    __nv_bfloat162 a, b2;
    a.x  = __float2bfloat16_rn((float)(v.x - 1) * 2.0e9f);
    a.y  = __float2bfloat16_rn((float)(v.y - 1) * 2.0e9f);
    b2.x = __float2bfloat16_rn((float)(v.z - 1) * 2.0e9f);
    b2.y = __float2bfloat16_rn((float)(v.w - 1) * 2.0e9f);
    uint2 o; o.x = *(uint32_t*)&a; o.y = *(uint32_t*)&b2;
    *(uint2*)&out[i] = o;
}

// ============================================================================
// HMMA GEMM: CTA 256x128, warp 64x64.  APASS=2: A fp16 hi/lo (2-pass).
// APASS=1: A single fp16 (1-pass).  B single fp16 always.
// ============================================================================
#define G_BUFSZ 81920
#define G_SMEM_TOTAL (2*G_BUFSZ)

template<int SPLITHEADS, int APASS>
__device__ __forceinline__ void gemm_body(
    const __half* __restrict__ Ah, const __half* __restrict__ Al,
    const __half* __restrict__ Bs,
    const float* __restrict__ bias, float* __restrict__ Y,
    __half* __restrict__ Yh, __half* __restrict__ Yl,
    char* smem)
{
    const uint32_t sb = smem_u32(smem);
    const int t     = threadIdx.x;
    const int wid   = t >> 5;
    const int lane  = t & 31;
    const int warpM = wid & 3;
    const int warpN = wid >> 2;
    const int n0    = blockIdx.x * 128;
    const int m0    = blockIdx.y * 256;

    auto stage = [&](int s) {
        const int k0 = s * 64;
        const uint32_t bufb = sb + (s & 1) * G_BUFSZ;
#pragma unroll
        for (int u = 0; u < 8 * APASS; u++) {
            int seg = t + u * 256;
            int arr = seg >> 11;
            int s2  = seg & 2047;
            int r   = s2 >> 3, c = s2 & 7;
            const __half* g = (arr ? Al : Ah) + (size_t)(m0 + r) * 1024 + k0 + c * 8;
            uint32_t dst = bufb + arr * 32768 + SWZ128((uint32_t)(r * 128 + c * 16));
            CP16(dst, g);
        }
#pragma unroll
        for (int u = 0; u < 4; u++) {
            int seg = t + u * 256;
            int r = seg >> 3, c = seg & 7;
            const __half* g = Bs + (size_t)(n0 + r) * 1024 + k0 + c * 8;
            uint32_t dst = bufb + 65536 + SWZ128((uint32_t)(r * 128 + c * 16));
            CP16(dst, g);
        }
        CP_COMMIT();
    };

    float acc[4][8][4];
#pragma unroll
    for (int mf = 0; mf < 4; mf++)
#pragma unroll
        for (int nf = 0; nf < 8; nf++)
#pragma unroll
            for (int e = 0; e < 4; e++) acc[mf][nf][e] = 0.f;

    const int mat   = lane >> 3;
    const int r8    = lane & 7;
    const int aRow0 = warpM * 64 + (mat & 1) * 8 + r8;
    const int aKh   = mat >> 1;
    const int bRow0 = warpN * 64 + (mat >> 1) * 8 + r8;
    const int bKh   = mat & 1;

    stage(0);

    for (int s = 0; s < 16; s++) {
        if (s + 1 < 16) { stage(s + 1); CP_WAIT1(); }
        else            { CP_WAIT0(); }
        __syncthreads();

        const uint32_t AH = sb + (s & 1) * G_BUFSZ;
        const uint32_t AL = AH + 32768, BS = AH + 65536;

#pragma unroll
        for (int ks = 0; ks < 4; ks++) {
            uint32_t bF[4][4];
#pragma unroll
            for (int g = 0; g < 4; g++) {
                int row = bRow0 + g * 16;
                uint32_t off = (uint32_t)(row * 128 +
                               (((2 * ks + bKh) ^ (row & 7)) * 16));
                ldsm_x4(bF[g], BS + off);
            }
#pragma unroll
            for (int mf = 0; mf < 4; mf++) {
                uint32_t aH[4], aL[4];
                int row = aRow0 + mf * 16;
                uint32_t off = (uint32_t)(row * 128 +
                               (((2 * ks + aKh) ^ (row & 7)) * 16));
                ldsm_x4(aH, AH + off);
                if (APASS == 2) ldsm_x4(aL, AL + off);
#pragma unroll
                for (int nf = 0; nf < 8; nf++)
                    mma_f16(acc[mf][nf], aH, &bF[nf >> 1][(nf & 1) * 2]);
                if (APASS == 2) {
#pragma unroll
                    for (int nf = 0; nf < 8; nf++)
                        mma_f16(acc[mf][nf], aL, &bF[nf >> 1][(nf & 1) * 2]);
                }
            }
        }
        __syncthreads();
    }

    const int rbase = lane >> 2;
    const int cpair = (lane & 3) * 2;
#pragma unroll
    for (int nf = 0; nf < 8; nf++) {
        int n = n0 + warpN * 64 + nf * 8 + cpair;
        float bx = __ldg(&bias[n]), by = __ldg(&bias[n + 1]);
#pragma unroll
        for (int mf = 0; mf < 4; mf++) {
            float* a = acc[mf][nf];
            int m = m0 + warpM * 64 + mf * 16 + rbase;
#pragma unroll
            for (int half_ = 0; half_ < 2; half_++) {
                int mm = m + half_ * 8;
                float vx = a[half_ * 2 + 0] + bx, vy = a[half_ * 2 + 1] + by;
                if (SPLITHEADS) {
                    int b = mm >> 11, l = mm & 2047;
                    int h = n >> 6,  d = n & 63;
                    size_t idx = (((size_t)(b * Hc + h)) * Lc + l) * Dc + d;
                    __half2 hv = __floats2half2_rn(vx, vy);
                    __half2 lv = __floats2half2_rn(
                        vx - __half2float(__low2half(hv)),
                        vy - __half2float(__high2half(hv)));
                    *(uint32_t*)&Yh[idx] = *(uint32_t*)&hv;
                    *(uint32_t*)&Yl[idx] = *(uint32_t*)&lv;
                } else {
                    *(float2*)&Y[(size_t)mm * 1024 + n] = make_float2(vx, vy);
                }
            }
        }
    }
}

struct GemmBatch {
    const __half *Ah[3], *Al[3], *Bs[3];
    const float* bias[3];
    __half *Yh[3], *Yl[3];
};

__global__ void __launch_bounds__(256, 1) gemm_proj_kernel(GemmBatch p)
{
    extern __shared__ char smem[];
    int z = blockIdx.z;
    gemm_body<1, 2>(p.Ah[z], p.Al[z], p.Bs[z], p.bias[z],
                    nullptr, p.Yh[z], p.Yl[z], smem);
}

__global__ void __launch_bounds__(256, 1)
gemm_out_kernel(const __half* As, const __half* Bs,
                const float* bias, float* Y)
{
    extern __shared__ char smem[];
    gemm_body<0, 1>(As, nullptr, Bs, bias, Y, nullptr, nullptr, smem);
}

// ============================================================================
// HMMA flash attention v8: Q fp16 hi/lo (2-pass S), K/V single fp16,
// P single fp16 (1-pass PV). 256q/CTA, 32 q-rows/warp. Z single fp16.
// ============================================================================
#define ATT_QH 0
#define ATT_QL 32768
#define ATT_B0 65536
#define ATT_KVBUF 16384
#define ATT_MS0 98304
#define ATT_MSBUF 36864
#define ATT_SMEM 172032

__global__ void __launch_bounds__(256, 1)
attn_mma_kernel(const __half* __restrict__ Qh, const __half* __restrict__ Ql,
                const __half* __restrict__ Kv, const __half* __restrict__ Vv,
                const __nv_bfloat16* __restrict__ Mb,
                __half* __restrict__ Z)
{
    extern __shared__ char smem[];
    const uint32_t sb = smem_u32(smem);
    const int t  = threadIdx.x;
    const int w  = t >> 5;
    const int l  = t & 31;
    const int bh = blockIdx.y;
    const int b  = bh >> 4;
    const int h  = bh & 15;
    const int q0 = blockIdx.x * 256;

    const __half* Qbh = Qh + (size_t)bh * Lc * Dc;
    const __half* Qbl = Ql + (size_t)bh * Lc * Dc;
    const __half* Kb  = Kv + (size_t)bh * Lc * Dc;
    const __half* Vb  = Vv + (size_t)bh * Lc * Dc;
    const __nv_bfloat16* Mbb = Mb + ((size_t)b * Lc + q0) * Lc;

    const float SC = 0.125f * 1.4426950408889634f;
    const int mat = l >> 3;
    const int r8  = l & 7;
    const int gr  = l >> 2;

    auto stage = [&](int s) {
        const int kt = s * 64;
        const uint32_t kvb = sb + ATT_B0 + (s & 1) * ATT_KVBUF;
        const uint32_t msb = sb + ATT_MS0 + (s & 1) * ATT_MSBUF;
#pragma unroll
        for (int u = 0; u < 4; u++) {
            int seg = t + u * 256;
            int arr = seg >> 9;
            int s2  = seg & 511;
            int r   = s2 >> 3, c = s2 & 7;
            const __half* g = (arr ? Vb : Kb) + (size_t)(kt + r) * Dc + c * 8;
            uint32_t dst = kvb + arr * 8192 + SWZ128((uint32_t)(r * 128 + c * 16));
            CP16(dst, g);
        }
#pragma unroll
        for (int u = 0; u < 8; u++) {
            int seg = t + u * 256;
            int r = seg >> 3, c = seg & 7;
            const __nv_bfloat16* g = Mbb + (size_t)r * Lc + kt + c * 8;
            CP16(msb + r * 144 + c * 16, g);
        }
        CP_COMMIT();
    };

#pragma unroll
    for (int u = 0; u < 16; u++) {
        int seg = t + u * 256;
        int arr = seg >> 11;
        int s2  = seg & 2047;
        int r   = s2 >> 3, c = s2 & 7;
        const __half* g = (arr ? Qbl : Qbh) + (size_t)(q0 + r) * Dc + c * 8;
        uint32_t dst = sb + (arr ? ATT_QL : ATT_QH) + SWZ128((uint32_t)(r * 128 + c * 16));
        CP16(dst, g);
    }
    stage(0);

    float accO[2][8][4];
#pragma unroll
    for (int mf = 0; mf < 2; mf++)
#pragma unroll
        for (int nf = 0; nf < 8; nf++)
#pragma unroll
            for (int e = 0; e < 4; e++) accO[mf][nf][e] = 0.f;
    float mA[2] = {-3.0e38f, -3.0e38f}, mB[2] = {-3.0e38f, -3.0e38f};
    float lA[2] = {0.f, 0.f},           lB[2] = {0.f, 0.f};

    for (int s = 0; s < 32; s++) {
        if (s + 1 < 32) { stage(s + 1); CP_WAIT1(); }
        else            { CP_WAIT0(); }
        __syncthreads();

        const uint32_t KHb = sb + ATT_B0 + (s & 1) * ATT_KVBUF;
        const uint32_t VHb = KHb + 8192;
        const uint32_t MSo = ATT_MS0 + (s & 1) * ATT_MSBUF;

        // --- S = Q K^T (2-pass: qh*k + ql*k) ---
        float accS[2][8][4];
#pragma unroll
        for (int mf = 0; mf < 2; mf++)
#pragma unroll
            for (int nf = 0; nf < 8; nf++)
#pragma unroll
                for (int e = 0; e < 4; e++) accS[mf][nf][e] = 0.f;

#pragma unroll
        for (int kf = 0; kf < 4; kf++) {
            uint32_t qh[2][4], ql[2][4];
#pragma unroll
            for (int mf = 0; mf < 2; mf++) {
                int row = w * 32 + mf * 16 + (mat & 1) * 8 + r8;
                int chk = kf * 2 + (mat >> 1);
                uint32_t off = (uint32_t)(row * 128 + ((chk ^ (row & 7)) * 16));
                ldsm_x4(qh[mf], sb + ATT_QH + off);
                ldsm_x4(ql[mf], sb + ATT_QL + off);
            }
#pragma unroll
            for (int g = 0; g < 4; g++) {
                uint32_t kh[4];
                int row = g * 16 + (mat >> 1) * 8 + r8;
                int chk = kf * 2 + (mat & 1);
                uint32_t off = (uint32_t)(row * 128 + ((chk ^ (row & 7)) * 16));
                ldsm_x4(kh, KHb + off);
#pragma unroll
                for (int mf = 0; mf < 2; mf++) {
                    mma_f16(accS[mf][2 * g],     qh[mf], kh);
                    mma_f16(accS[mf][2 * g],     ql[mf], kh);
                    mma_f16(accS[mf][2 * g + 1], qh[mf], kh + 2);
                    mma_f16(accS[mf][2 * g + 1], ql[mf], kh + 2);
                }
            }
        }

        // --- softmax (fp32, log2 domain; MUFU ex2) ---
#pragma unroll
        for (int mf = 0; mf < 2; mf++) {
            const int rw0 = w * 32 + mf * 16 + gr;
            float t0 = -3.0e38f, t1 = -3.0e38f;
#pragma unroll
            for (int nf = 0; nf < 8; nf++) {
                int colb = (nf * 8 + (l & 3) * 2) * 2;
                __nv_bfloat162 ms0 = *(__nv_bfloat162*)(smem + MSo + rw0 * 144 + colb);
                __nv_bfloat162 ms1 = *(__nv_bfloat162*)(smem + MSo + (rw0 + 8) * 144 + colb);
                accS[mf][nf][0] = fmaf(accS[mf][nf][0], SC, __bfloat162float(ms0.x));
                accS[mf][nf][1] = fmaf(accS[mf][nf][1], SC, __bfloat162float(ms0.y));
                accS[mf][nf][2] = fmaf(accS[mf][nf][2], SC, __bfloat162float(ms1.x));
                accS[mf][nf][3] = fmaf(accS[mf][nf][3], SC, __bfloat162float(ms1.y));
                t0 = fmaxf(t0, fmaxf(accS[mf][nf][0], accS[mf][nf][1]));
                t1 = fmaxf(t1, fmaxf(accS[mf][nf][2], accS[mf][nf][3]));
            }
            t0 = fmaxf(t0, __shfl_xor_sync(0xffffffffu, t0, 1));
            t0 = fmaxf(t0, __shfl_xor_sync(0xffffffffu, t0, 2));
            t1 = fmaxf(t1, __shfl_xor_sync(0xffffffffu, t1, 1));
            t1 = fmaxf(t1, __shfl_xor_sync(0xffffffffu, t1, 2));

            float mn0 = fmaxf(mA[mf], t0), mn1 = fmaxf(mB[mf], t1);
            float f0 = ex2f(mA[mf] - mn0), f1 = ex2f(mB[mf] - mn1);
            mA[mf] = mn0; mB[mf] = mn1;

            float rs0 = 0.f, rs1 = 0.f;
#pragma unroll
            for (int nf = 0; nf < 8; nf++) {
                accS[mf][nf][0] = ex2f(accS[mf][nf][0] - mA[mf]);
                accS[mf][nf][1] = ex2f(accS[mf][nf][1] - mA[mf]);
                accS[mf][nf][2] = ex2f(accS[mf][nf][2] - mB[mf]);
                accS[mf][nf][3] = ex2f(accS[mf][nf][3] - mB[mf]);
                rs0 += accS[mf][nf][0] + accS[mf][nf][1];
                rs1 += accS[mf][nf][2] + accS[mf][nf][3];
                accO[mf][nf][0] *= f0; accO[mf][nf][1] *= f0;
                accO[mf][nf][2] *= f1; accO[mf][nf][3] *= f1;
            }
            rs0 += __shfl_xor_sync(0xffffffffu, rs0, 1);
            rs0 += __shfl_xor_sync(0xffffffffu, rs0, 2);
            rs1 += __shfl_xor_sync(0xffffffffu, rs1, 1);
            rs1 += __shfl_xor_sync(0xffffffffu, rs1, 2);
            lA[mf] = lA[mf] * f0 + rs0;
            lB[mf] = lB[mf] * f1 + rs1;
        }

        // --- O += P @ V (1-pass: ph*v; P single fp16) ---
#pragma unroll
        for (int kf = 0; kf < 4; kf++) {
            uint32_t ah[2][4];
#pragma unroll
            for (int mf = 0; mf < 2; mf++) {
                const float* pA = accS[mf][2 * kf];
                const float* pB = accS[mf][2 * kf + 1];
                ah[mf][0] = pack_h2(pA[0], pA[1]);
                ah[mf][1] = pack_h2(pA[2], pA[3]);
                ah[mf][2] = pack_h2(pB[0], pB[1]);
                ah[mf][3] = pack_h2(pB[2], pB[3]);
            }
            int rowv = kf * 16 + (l & 15);
#pragma unroll
            for (int g = 0; g < 4; g++) {
                uint32_t vh[4];
                int chv = g * 2 + (l >> 4);
                uint32_t off = (uint32_t)(rowv * 128 + ((chv ^ (rowv & 7)) * 16));
                ldsm_x4_t(vh, VHb + off);
#pragma unroll
                for (int mf = 0; mf < 2; mf++) {
                    mma_f16(accO[mf][2 * g],     ah[mf], vh);
                    mma_f16(accO[mf][2 * g + 1], ah[mf], vh + 2);
                }
            }
        }
        __syncthreads();
    }

    // finalize: divide, write Z single fp16
#pragma unroll
    for (int mf = 0; mf < 2; mf++) {
        float inv0 = 1.f / lA[mf], inv1 = 1.f / lB[mf];
        int qg0 = q0 + w * 32 + mf * 16 + gr;
#pragma unroll
        for (int nf = 0; nf < 8; nf++) {
            int d = nf * 8 + (l & 3) * 2;
            size_t i0 = ((size_t)(b * Lc + qg0)) * Cc + h * 64 + d;
            size_t i1 = ((size_t)(b * Lc + qg0 + 8)) * Cc + h * 64 + d;
            uint32_t v0 = pack_h2(accO[mf][nf][0] * inv0, accO[mf][nf][1] * inv0);
            uint32_t v1 = pack_h2(accO[mf][nf][2] * inv1, accO[mf][nf][3] * inv1);
            *(uint32_t*)&Z[i0] = v0;
            *(uint32_t*)&Z[i1] = v1;
        }
    }
}

// ============================================================================
// Launcher
// ============================================================================
extern "C" void kernel_launch(void* const* d_in, const int* in_sizes, int n_in,
                              void* d_out, int out_size)
{
    const float* query = (const float*)d_in[0];
    const float* key_  = (const float*)d_in[1];
    const float* value = (const float*)d_in[2];
    const int*   mask  = (const int*)  d_in[3];
    const float* WQ = (const float*)d_in[4];
    const float* bQ = (const float*)d_in[5];
    const float* WK = (const float*)d_in[6];
    const float* bK = (const float*)d_in[7];
    const float* WV = (const float*)d_in[8];
    const float* bV = (const float*)d_in[9];
    const float* WO = (const float*)d_in[10];
    const float* bO = (const float*)d_in[11];
    float* out = (float*)d_out;

    void *xqh, *xql, *xkh, *xkl, *xvh, *xvl;
    cudaGetSymbolAddress(&xqh, g_Xq_h); cudaGetSymbolAddress(&xql, g_Xq_l);
    cudaGetSymbolAddress(&xkh, g_Xk_h); cudaGetSymbolAddress(&xkl, g_Xk_l);
    cudaGetSymbolAddress(&xvh, g_Xv_h); cudaGetSymbolAddress(&xvl, g_Xv_l);
    void *qbh, *qbl, *kbh, *kbl, *vbh, *vbl, *zz, *pM;
    cudaGetSymbolAddress(&qbh, g_Qb_h); cudaGetSymbolAddress(&qbl, g_Qb_l);
    cudaGetSymbolAddress(&kbh, g_Kb_h); cudaGetSymbolAddress(&kbl, g_Kb_l);
    cudaGetSymbolAddress(&vbh, g_Vb_h); cudaGetSymbolAddress(&vbl, g_Vb_l);
    cudaGetSymbolAddress(&zz, g_Z);
    cudaGetSymbolAddress(&pM, g_Mb);
    void *wq, *wk, *wv, *wo;
    cudaGetSymbolAddress(&wq, g_WtQ);
    cudaGetSymbolAddress(&wk, g_WtK);
    cudaGetSymbolAddress(&wv, g_WtV);
    cudaGetSymbolAddress(&wo, g_WtO);

    cudaFuncSetAttribute(attn_mma_kernel,
                         cudaFuncAttributeMaxDynamicSharedMemorySize, ATT_SMEM);
    cudaFuncSetAttribute(gemm_proj_kernel,
                         cudaFuncAttributeMaxDynamicSharedMemorySize, G_SMEM_TOTAL);
    cudaFuncSetAttribute(gemm_out_kernel,
                         cudaFuncAttributeMaxDynamicSharedMemorySize, G_SMEM_TOTAL);

    // --- Prep (fused) ---
    XSplitBatch xp;
    xp.X[0] = query; xp.X[1] = key_; xp.X[2] = value;
    xp.Xh[0] = (__half*)xqh; xp.Xl[0] = (__half*)xql;
    xp.Xh[1] = (__half*)xkh; xp.Xl[1] = (__half*)xkl;
    xp.Xh[2] = (__half*)xvh; xp.Xl[2] = (__half*)xvl;
    xsplit_kernel<<<dim3(Mc * Cc / (256 * 8), 3), 256>>>(xp);

    maskprep_kernel<<<(Bc * Lc * Lc) / (256 * 4), 256>>>(mask, (__nv_bfloat16*)pM);

    WSplitBatch wp;
    wp.W[0] = WQ; wp.W[1] = WK; wp.W[2] = WV; wp.W[3] = WO;
    wp.T[0] = (__half*)wq; wp.T[1] = (__half*)wk;
    wp.T[2] = (__half*)wv; wp.T[3] = (__half*)wo;
    wsplit_kernel<<<dim3(32, 32, 4), dim3(32, 8)>>>(wp);

    // --- Fused projection GEMMs ---
    GemmBatch gp;
    gp.Ah[0] = (const __half*)xqh; gp.Al[0] = (const __half*)xql;
    gp.Ah[1] = (const __half*)xkh; gp.Al[1] = (const __half*)xkl;
    gp.Ah[2] = (const __half*)xvh; gp.Al[2] = (const __half*)xvl;
    gp.Bs[0] = (const __half*)wq;
    gp.Bs[1] = (const __half*)wk;
    gp.Bs[2] = (const __half*)wv;
    gp.bias[0] = bQ; gp.bias[1] = bK; gp.bias[2] = bV;
    gp.Yh[0] = (__half*)qbh; gp.Yl[0] = (__half*)qbl;
    gp.Yh[1] = (__half*)kbh; gp.Yl[1] = (__half*)kbl;
    gp.Yh[2] = (__half*)vbh; gp.Yl[2] = (__half*)vbl;
    gemm_proj_kernel<<<dim3(Cc / 128, Mc / 256, 3), 256, G_SMEM_TOTAL>>>(gp);

    dim3 attn_grid(Lc / 256, Bc * Hc);
    attn_mma_kernel<<<attn_grid, 256, ATT_SMEM>>>(
        (const __half*)qbh, (const __half*)qbl,
        (const __half*)kbh, (const __half*)vbh,
        (const __nv_bfloat16*)pM, (__half*)zz);

    gemm_out_kernel<<<dim3(Cc / 128, Mc / 256), 256, G_SMEM_TOTAL>>>(
        (const __half*)zz, (const __half*)wo, bO, out);
}

// round 17
// speedup vs baseline: 1.9054x; 1.2707x over previous
#include <cuda_runtime.h>
#include <cuda_bf16.h>
#include <cuda_fp16.h>
#include <math.h>
#include <stdint.h>

// Problem constants
#define Bc 2
#define Lc 2048
#define Cc 1024
#define Hc 16
#define Dc 64
#define Mc (Bc*Lc)

// Scratch (device globals) — single fp16 everywhere
__device__ __half g_Xq[Mc*Cc];
__device__ __half g_Xk[Mc*Cc];
__device__ __half g_Xv[Mc*Cc];
__device__ __half g_Qb[Bc*Hc*Lc*Dc];
__device__ __half g_Kb[Bc*Hc*Lc*Dc];
__device__ __half g_Vb[Bc*Hc*Lc*Dc];
__device__ __half g_Z[Bc*Lc*Cc];
__device__ __nv_bfloat16 g_Mb[Bc*Lc*Lc];

__device__ __half g_WtQ[Cc*Cc];
__device__ __half g_WtK[Cc*Cc];
__device__ __half g_WtV[Cc*Cc];
__device__ __half g_WtO[Cc*Cc];

// ============================================================================
// Helpers
// ============================================================================
__device__ __forceinline__ uint32_t smem_u32(const void* p) {
    uint32_t a;
    asm("{ .reg .u64 t; cvta.to.shared.u64 t, %1; cvt.u32.u64 %0, t; }"
        : "=r"(a) : "l"(p));
    return a;
}
#define SWZ128(off) ((off) ^ (((off) >> 3) & 0x70))

#define CP16(dst, src) \
    asm volatile("cp.async.cg.shared.global [%0], [%1], 16;" \
                 :: "r"(dst), "l"(src) : "memory")
#define CP_COMMIT() asm volatile("cp.async.commit_group;" ::: "memory")
#define CP_WAIT1()  asm volatile("cp.async.wait_group 1;" ::: "memory")
#define CP_WAIT0()  asm volatile("cp.async.wait_group 0;" ::: "memory")

__device__ __forceinline__ void ldsm_x4(uint32_t* r, uint32_t addr) {
    asm volatile("ldmatrix.sync.aligned.m8n8.x4.shared.b16 {%0,%1,%2,%3}, [%4];"
                 : "=r"(r[0]), "=r"(r[1]), "=r"(r[2]), "=r"(r[3]) : "r"(addr));
}
__device__ __forceinline__ void ldsm_x4_t(uint32_t* r, uint32_t addr) {
    asm volatile("ldmatrix.sync.aligned.m8n8.x4.trans.shared.b16 {%0,%1,%2,%3}, [%4];"
                 : "=r"(r[0]), "=r"(r[1]), "=r"(r[2]), "=r"(r[3]) : "r"(addr));
}
__device__ __forceinline__ void mma_f16(float* c, const uint32_t* a,
                                        const uint32_t* b) {
    asm volatile(
        "mma.sync.aligned.m16n8k16.row.col.f32.f16.f16.f32 "
        "{%0,%1,%2,%3}, {%4,%5,%6,%7}, {%8,%9}, {%0,%1,%2,%3};"
        : "+f"(c[0]), "+f"(c[1]), "+f"(c[2]), "+f"(c[3])
        : "r"(a[0]), "r"(a[1]), "r"(a[2]), "r"(a[3]), "r"(b[0]), "r"(b[1]));
}
__device__ __forceinline__ uint32_t pack_h2(float x, float y) {
    __half2 v = __floats2half2_rn(x, y);
    return *(uint32_t*)&v;
}
__device__ __forceinline__ float ex2f(float x) {
    float y;
    asm("ex2.approx.f32 %0, %1;" : "=f"(y) : "f"(x));
    return y;
}

// ============================================================================
// Prep kernels
// ============================================================================
struct XCvtBatch {
    const float* X[3];
    __half* Xo[3];
};
__global__ void xcvt_kernel(XCvtBatch p)
{
    int z = blockIdx.y;
    size_t i = ((size_t)blockIdx.x * 256 + threadIdx.x) * 8;
    const float4* src = (const float4*)&p.X[z][i];
    float4 x0 = src[0], x1 = src[1];
    __half hh[8];
    hh[0] = __float2half_rn(x0.x); hh[1] = __float2half_rn(x0.y);
    hh[2] = __float2half_rn(x0.z); hh[3] = __float2half_rn(x0.w);
    hh[4] = __float2half_rn(x1.x); hh[5] = __float2half_rn(x1.y);
    hh[6] = __float2half_rn(x1.z); hh[7] = __float2half_rn(x1.w);
    *(uint4*)&p.Xo[z][i] = *(uint4*)hh;
}

struct WSplitBatch {
    const float* W[4];
    __half* T[4];
};
__global__ void wsplit_kernel(WSplitBatch p)
{
    __shared__ float tile[32][33];
    int z = blockIdx.z;
    int n0 = blockIdx.x * 32, k0 = blockIdx.y * 32;
    int tx = threadIdx.x, ty = threadIdx.y;
#pragma unroll
    for (int i = 0; i < 32; i += 8)
        tile[ty + i][tx] = p.W[z][(size_t)(k0 + ty + i) * Cc + n0 + tx];
    __syncthreads();
#pragma unroll
    for (int i = 0; i < 32; i += 8) {
        size_t idx = (size_t)(n0 + ty + i) * Cc + k0 + tx;
        p.T[z][idx] = __float2half_rn(tile[tx][ty + i]);
    }
}

__global__ void maskprep_kernel(const int* __restrict__ m,
                                __nv_bfloat16* __restrict__ out)
{
    int i = (blockIdx.x * 256 + threadIdx.x) * 4;
    int4 v = *(const int4*)&m[i];
    __nv_bfloat162 a, b2;
    a.x  = __float2bfloat16_rn((float)(v.x - 1) * 2.0e9f);
    a.y  = __float2bfloat16_rn((float)(v.y - 1) * 2.0e9f);
    b2.x = __float2bfloat16_rn((float)(v.z - 1) * 2.0e9f);
    b2.y = __float2bfloat16_rn((float)(v.w - 1) * 2.0e9f);
    uint2 o; o.x = *(uint32_t*)&a; o.y = *(uint32_t*)&b2;
    *(uint2*)&out[i] = o;
}

// ============================================================================
// HMMA GEMM (fp16 1-pass): Y = A @ B^T + bias, A and B single fp16.
// CTA 256m x 128n, 8 warps (4x2), warp tile 64x64.
// ============================================================================
#define G_BUFSZ 49152            // A 32K | B 16K
#define G_SMEM_TOTAL (2*G_BUFSZ) // 96 KB

template<int SPLITHEADS>
__device__ __forceinline__ void gemm_body(
    const __half* __restrict__ As, const __half* __restrict__ Bs,
    const float* __restrict__ bias, float* __restrict__ Y,
    __half* __restrict__ Yh, char* smem)
{
    const uint32_t sb = smem_u32(smem);
    const int t     = threadIdx.x;
    const int wid   = t >> 5;
    const int lane  = t & 31;
    const int warpM = wid & 3;
    const int warpN = wid >> 2;
    const int n0    = blockIdx.x * 128;
    const int m0    = blockIdx.y * 256;

    auto stage = [&](int s) {
        const int k0 = s * 64;
        const uint32_t bufb = sb + (s & 1) * G_BUFSZ;
        // A: 256 rows x 8 chunks = 2048 -> 8/thread
#pragma unroll
        for (int u = 0; u < 8; u++) {
            int seg = t + u * 256;
            int r = seg >> 3, c = seg & 7;
            const __half* g = As + (size_t)(m0 + r) * 1024 + k0 + c * 8;
            uint32_t dst = bufb + SWZ128((uint32_t)(r * 128 + c * 16));
            CP16(dst, g);
        }
        // B: 128 rows x 8 chunks = 1024 -> 4/thread
#pragma unroll
        for (int u = 0; u < 4; u++) {
            int seg = t + u * 256;
            int r = seg >> 3, c = seg & 7;
            const __half* g = Bs + (size_t)(n0 + r) * 1024 + k0 + c * 8;
            uint32_t dst = bufb + 32768 + SWZ128((uint32_t)(r * 128 + c * 16));
            CP16(dst, g);
        }
        CP_COMMIT();
    };

    float acc[4][8][4];
#pragma unroll
    for (int mf = 0; mf < 4; mf++)
#pragma unroll
        for (int nf = 0; nf < 8; nf++)
#pragma unroll
            for (int e = 0; e < 4; e++) acc[mf][nf][e] = 0.f;

    const int mat   = lane >> 3;
    const int r8    = lane & 7;
    const int aRow0 = warpM * 64 + (mat & 1) * 8 + r8;
    const int aKh   = mat >> 1;
    const int bRow0 = warpN * 64 + (mat >> 1) * 8 + r8;
    const int bKh   = mat & 1;

    stage(0);

    for (int s = 0; s < 16; s++) {
        if (s + 1 < 16) { stage(s + 1); CP_WAIT1(); }
        else            { CP_WAIT0(); }
        __syncthreads();

        const uint32_t AS = sb + (s & 1) * G_BUFSZ;
        const uint32_t BS = AS + 32768;

#pragma unroll
        for (int ks = 0; ks < 4; ks++) {
            uint32_t bF[4][4];
#pragma unroll
            for (int g = 0; g < 4; g++) {
                int row = bRow0 + g * 16;
                uint32_t off = (uint32_t)(row * 128 +
                               (((2 * ks + bKh) ^ (row & 7)) * 16));
                ldsm_x4(bF[g], BS + off);
            }
#pragma unroll
            for (int mf = 0; mf < 4; mf++) {
                uint32_t aF[4];
                int row = aRow0 + mf * 16;
                uint32_t off = (uint32_t)(row * 128 +
                               (((2 * ks + aKh) ^ (row & 7)) * 16));
                ldsm_x4(aF, AS + off);
#pragma unroll
                for (int nf = 0; nf < 8; nf++)
                    mma_f16(acc[mf][nf], aF, &bF[nf >> 1][(nf & 1) * 2]);
            }
        }
        __syncthreads();
    }

    const int rbase = lane >> 2;
    const int cpair = (lane & 3) * 2;
#pragma unroll
    for (int nf = 0; nf < 8; nf++) {
        int n = n0 + warpN * 64 + nf * 8 + cpair;
        float bx = __ldg(&bias[n]), by = __ldg(&bias[n + 1]);
#pragma unroll
        for (int mf = 0; mf < 4; mf++) {
            float* a = acc[mf][nf];
            int m = m0 + warpM * 64 + mf * 16 + rbase;
#pragma unroll
            for (int half_ = 0; half_ < 2; half_++) {
                int mm = m + half_ * 8;
                float vx = a[half_ * 2 + 0] + bx, vy = a[half_ * 2 + 1] + by;
                if (SPLITHEADS) {
                    int b = mm >> 11, l = mm & 2047;
                    int h = n >> 6,  d = n & 63;
                    size_t idx = (((size_t)(b * Hc + h)) * Lc + l) * Dc + d;
                    *(uint32_t*)&Yh[idx] = pack_h2(vx, vy);
                } else {
                    *(float2*)&Y[(size_t)mm * 1024 + n] = make_float2(vx, vy);
                }
            }
        }
    }
}

struct GemmBatch {
    const __half *As[3], *Bs[3];
    const float* bias[3];
    __half *Yh[3];
};

__global__ void __launch_bounds__(256, 1) gemm_proj_kernel(GemmBatch p)
{
    extern __shared__ char smem[];
    int z = blockIdx.z;
    gemm_body<1>(p.As[z], p.Bs[z], p.bias[z], nullptr, p.Yh[z], smem);
}

__global__ void __launch_bounds__(256, 1)
gemm_out_kernel(const __half* As, const __half* Bs,
                const float* bias, float* Y)
{
    extern __shared__ char smem[];
    gemm_body<0>(As, Bs, bias, Y, nullptr, smem);
}

// ============================================================================
// HMMA flash attention v9 (all single fp16 operands): 1-pass S, 1-pass PV.
// 256q/CTA, 32 q-rows/warp. fp32 accumulation + softmax throughout.
// ============================================================================
#define ATT_Q 0                  // 256x64 fp16 = 32KB
#define ATT_B0 32768
#define ATT_KVBUF 16384
#define ATT_MS0 65536
#define ATT_MSBUF 36864
#define ATT_SMEM 139264

__global__ void __launch_bounds__(256, 1)
attn_mma_kernel(const __half* __restrict__ Qv,
                const __half* __restrict__ Kv, const __half* __restrict__ Vv,
                const __nv_bfloat16* __restrict__ Mb,
                __half* __restrict__ Z)
{
    extern __shared__ char smem[];
    const uint32_t sb = smem_u32(smem);
    const int t  = threadIdx.x;
    const int w  = t >> 5;
    const int l  = t & 31;
    const int bh = blockIdx.y;
    const int b  = bh >> 4;
    const int h  = bh & 15;
    const int q0 = blockIdx.x * 256;

    const __half* Qb = Qv + (size_t)bh * Lc * Dc;
    const __half* Kb = Kv + (size_t)bh * Lc * Dc;
    const __half* Vb = Vv + (size_t)bh * Lc * Dc;
    const __nv_bfloat16* Mbb = Mb + ((size_t)b * Lc + q0) * Lc;

    const float SC = 0.125f * 1.4426950408889634f;
    const int mat = l >> 3;
    const int r8  = l & 7;
    const int gr  = l >> 2;

    auto stage = [&](int s) {
        const int kt = s * 64;
        const uint32_t kvb = sb + ATT_B0 + (s & 1) * ATT_KVBUF;
        const uint32_t msb = sb + ATT_MS0 + (s & 1) * ATT_MSBUF;
#pragma unroll
        for (int u = 0; u < 4; u++) {
            int seg = t + u * 256;
            int arr = seg >> 9;
            int s2  = seg & 511;
            int r   = s2 >> 3, c = s2 & 7;
            const __half* g = (arr ? Vb : Kb) + (size_t)(kt + r) * Dc + c * 8;
            uint32_t dst = kvb + arr * 8192 + SWZ128((uint32_t)(r * 128 + c * 16));
            CP16(dst, g);
        }
#pragma unroll
        for (int u = 0; u < 8; u++) {
            int seg = t + u * 256;
            int r = seg >> 3, c = seg & 7;
            const __nv_bfloat16* g = Mbb + (size_t)r * Lc + kt + c * 8;
            CP16(msb + r * 144 + c * 16, g);
        }
        CP_COMMIT();
    };

    // Prologue: Q (256 rows x 8 chunks = 2048 -> 8/thread)
#pragma unroll
    for (int u = 0; u < 8; u++) {
        int seg = t + u * 256;
        int r = seg >> 3, c = seg & 7;
        const __half* g = Qb + (size_t)(q0 + r) * Dc + c * 8;
        uint32_t dst = sb + ATT_Q + SWZ128((uint32_t)(r * 128 + c * 16));
        CP16(dst, g);
    }
    stage(0);

    float accO[2][8][4];
#pragma unroll
    for (int mf = 0; mf < 2; mf++)
#pragma unroll
        for (int nf = 0; nf < 8; nf++)
#pragma unroll
            for (int e = 0; e < 4; e++) accO[mf][nf][e] = 0.f;
    float mA[2] = {-3.0e38f, -3.0e38f}, mB[2] = {-3.0e38f, -3.0e38f};
    float lA[2] = {0.f, 0.f},           lB[2] = {0.f, 0.f};

    for (int s = 0; s < 32; s++) {
        if (s + 1 < 32) { stage(s + 1); CP_WAIT1(); }
        else            { CP_WAIT0(); }
        __syncthreads();

        const uint32_t KHb = sb + ATT_B0 + (s & 1) * ATT_KVBUF;
        const uint32_t VHb = KHb + 8192;
        const uint32_t MSo = ATT_MS0 + (s & 1) * ATT_MSBUF;

        // --- S = Q K^T (1-pass) ---
        float accS[2][8][4];
#pragma unroll
        for (int mf = 0; mf < 2; mf++)
#pragma unroll
            for (int nf = 0; nf < 8; nf++)
#pragma unroll
                for (int e = 0; e < 4; e++) accS[mf][nf][e] = 0.f;

#pragma unroll
        for (int kf = 0; kf < 4; kf++) {
            uint32_t qf[2][4];
#pragma unroll
            for (int mf = 0; mf < 2; mf++) {
                int row = w * 32 + mf * 16 + (mat & 1) * 8 + r8;
                int chk = kf * 2 + (mat >> 1);
                uint32_t off = (uint32_t)(row * 128 + ((chk ^ (row & 7)) * 16));
                ldsm_x4(qf[mf], sb + ATT_Q + off);
            }
#pragma unroll
            for (int g = 0; g < 4; g++) {
                uint32_t kh[4];
                int row = g * 16 + (mat >> 1) * 8 + r8;
                int chk = kf * 2 + (mat & 1);
                uint32_t off = (uint32_t)(row * 128 + ((chk ^ (row & 7)) * 16));
                ldsm_x4(kh, KHb + off);
#pragma unroll
                for (int mf = 0; mf < 2; mf++) {
                    mma_f16(accS[mf][2 * g],     qf[mf], kh);
                    mma_f16(accS[mf][2 * g + 1], qf[mf], kh + 2);
                }
            }
        }

        // --- softmax (fp32, log2 domain; MUFU ex2) ---
#pragma unroll
        for (int mf = 0; mf < 2; mf++) {
            const int rw0 = w * 32 + mf * 16 + gr;
            float t0 = -3.0e38f, t1 = -3.0e38f;
#pragma unroll
            for (int nf = 0; nf < 8; nf++) {
                int colb = (nf * 8 + (l & 3) * 2) * 2;
                __nv_bfloat162 ms0 = *(__nv_bfloat162*)(smem + MSo + rw0 * 144 + colb);
                __nv_bfloat162 ms1 = *(__nv_bfloat162*)(smem + MSo + (rw0 + 8) * 144 + colb);
                accS[mf][nf][0] = fmaf(accS[mf][nf][0], SC, __bfloat162float(ms0.x));
                accS[mf][nf][1] = fmaf(accS[mf][nf][1], SC, __bfloat162float(ms0.y));
                accS[mf][nf][2] = fmaf(accS[mf][nf][2], SC, __bfloat162float(ms1.x));
                accS[mf][nf][3] = fmaf(accS[mf][nf][3], SC, __bfloat162float(ms1.y));
                t0 = fmaxf(t0, fmaxf(accS[mf][nf][0], accS[mf][nf][1]));
                t1 = fmaxf(t1, fmaxf(accS[mf][nf][2], accS[mf][nf][3]));
            }
            t0 = fmaxf(t0, __shfl_xor_sync(0xffffffffu, t0, 1));
            t0 = fmaxf(t0, __shfl_xor_sync(0xffffffffu, t0, 2));
            t1 = fmaxf(t1, __shfl_xor_sync(0xffffffffu, t1, 1));
            t1 = fmaxf(t1, __shfl_xor_sync(0xffffffffu, t1, 2));

            float mn0 = fmaxf(mA[mf], t0), mn1 = fmaxf(mB[mf], t1);
            float f0 = ex2f(mA[mf] - mn0), f1 = ex2f(mB[mf] - mn1);
            mA[mf] = mn0; mB[mf] = mn1;

            float rs0 = 0.f, rs1 = 0.f;
#pragma unroll
            for (int nf = 0; nf < 8; nf++) {
                accS[mf][nf][0] = ex2f(accS[mf][nf][0] - mA[mf]);
                accS[mf][nf][1] = ex2f(accS[mf][nf][1] - mA[mf]);
                accS[mf][nf][2] = ex2f(accS[mf][nf][2] - mB[mf]);
                accS[mf][nf][3] = ex2f(accS[mf][nf][3] - mB[mf]);
                rs0 += accS[mf][nf][0] + accS[mf][nf][1];
                rs1 += accS[mf][nf][2] + accS[mf][nf][3];
                accO[mf][nf][0] *= f0; accO[mf][nf][1] *= f0;
                accO[mf][nf][2] *= f1; accO[mf][nf][3] *= f1;
            }
            rs0 += __shfl_xor_sync(0xffffffffu, rs0, 1);
            rs0 += __shfl_xor_sync(0xffffffffu, rs0, 2);
            rs1 += __shfl_xor_sync(0xffffffffu, rs1, 1);
            rs1 += __shfl_xor_sync(0xffffffffu, rs1, 2);
            lA[mf] = lA[mf] * f0 + rs0;
            lB[mf] = lB[mf] * f1 + rs1;
        }

        // --- O += P @ V (1-pass; P single fp16) ---
#pragma unroll
        for (int kf = 0; kf < 4; kf++) {
            uint32_t ah[2][4];
#pragma unroll
            for (int mf = 0; mf < 2; mf++) {
                const float* pA = accS[mf][2 * kf];
                const float* pB = accS[mf][2 * kf + 1];
                ah[mf][0] = pack_h2(pA[0], pA[1]);
                ah[mf][1] = pack_h2(pA[2], pA[3]);
                ah[mf][2] = pack_h2(pB[0], pB[1]);
                ah[mf][3] = pack_h2(pB[2], pB[3]);
            }
            int rowv = kf * 16 + (l & 15);
#pragma unroll
            for (int g = 0; g < 4; g++) {
                uint32_t vh[4];
                int chv = g * 2 + (l >> 4);
                uint32_t off = (uint32_t)(rowv * 128 + ((chv ^ (rowv & 7)) * 16));
                ldsm_x4_t(vh, VHb + off);
#pragma unroll
                for (int mf = 0; mf < 2; mf++) {
                    mma_f16(accO[mf][2 * g],     ah[mf], vh);
                    mma_f16(accO[mf][2 * g + 1], ah[mf], vh + 2);
                }
            }
        }
        __syncthreads();
    }

    // finalize: divide, write Z single fp16
#pragma unroll
    for (int mf = 0; mf < 2; mf++) {
        float inv0 = 1.f / lA[mf], inv1 = 1.f / lB[mf];
        int qg0 = q0 + w * 32 + mf * 16 + gr;
#pragma unroll
        for (int nf = 0; nf < 8; nf++) {
            int d = nf * 8 + (l & 3) * 2;
            size_t i0 = ((size_t)(b * Lc + qg0)) * Cc + h * 64 + d;
            size_t i1 = ((size_t)(b * Lc + qg0 + 8)) * Cc + h * 64 + d;
            *(uint32_t*)&Z[i0] = pack_h2(accO[mf][nf][0] * inv0, accO[mf][nf][1] * inv0);
            *(uint32_t*)&Z[i1] = pack_h2(accO[mf][nf][2] * inv1, accO[mf][nf][3] * inv1);
        }
    }
}

// ============================================================================
// Launcher
// ============================================================================
extern "C" void kernel_launch(void* const* d_in, const int* in_sizes, int n_in,
                              void* d_out, int out_size)
{
    const float* query = (const float*)d_in[0];
    const float* key_  = (const float*)d_in[1];
    const float* value = (const float*)d_in[2];
    const int*   mask  = (const int*)  d_in[3];
    const float* WQ = (const float*)d_in[4];
    const float* bQ = (const float*)d_in[5];
    const float* WK = (const float*)d_in[6];
    const float* bK = (const float*)d_in[7];
    const float* WV = (const float*)d_in[8];
    const float* bV = (const float*)d_in[9];
    const float* WO = (const float*)d_in[10];
    const float* bO = (const float*)d_in[11];
    float* out = (float*)d_out;

    void *xq, *xk, *xv, *qb, *kb, *vb, *zz, *pM;
    cudaGetSymbolAddress(&xq, g_Xq);
    cudaGetSymbolAddress(&xk, g_Xk);
    cudaGetSymbolAddress(&xv, g_Xv);
    cudaGetSymbolAddress(&qb, g_Qb);
    cudaGetSymbolAddress(&kb, g_Kb);
    cudaGetSymbolAddress(&vb, g_Vb);
    cudaGetSymbolAddress(&zz, g_Z);
    cudaGetSymbolAddress(&pM, g_Mb);
    void *wq, *wk, *wv, *wo;
    cudaGetSymbolAddress(&wq, g_WtQ);
    cudaGetSymbolAddress(&wk, g_WtK);
    cudaGetSymbolAddress(&wv, g_WtV);
    cudaGetSymbolAddress(&wo, g_WtO);

    cudaFuncSetAttribute(attn_mma_kernel,
                         cudaFuncAttributeMaxDynamicSharedMemorySize, ATT_SMEM);
    cudaFuncSetAttribute(gemm_proj_kernel,
                         cudaFuncAttributeMaxDynamicSharedMemorySize, G_SMEM_TOTAL);
    cudaFuncSetAttribute(gemm_out_kernel,
                         cudaFuncAttributeMaxDynamicSharedMemorySize, G_SMEM_TOTAL);

    // --- Prep ---
    XCvtBatch xp;
    xp.X[0] = query; xp.X[1] = key_; xp.X[2] = value;
    xp.Xo[0] = (__half*)xq; xp.Xo[1] = (__half*)xk; xp.Xo[2] = (__half*)xv;
    xcvt_kernel<<<dim3(Mc * Cc / (256 * 8), 3), 256>>>(xp);

    maskprep_kernel<<<(Bc * Lc * Lc) / (256 * 4), 256>>>(mask, (__nv_bfloat16*)pM);

    WSplitBatch wp;
    wp.W[0] = WQ; wp.W[1] = WK; wp.W[2] = WV; wp.W[3] = WO;
    wp.T[0] = (__half*)wq; wp.T[1] = (__half*)wk;
    wp.T[2] = (__half*)wv; wp.T[3] = (__half*)wo;
    wsplit_kernel<<<dim3(32, 32, 4), dim3(32, 8)>>>(wp);

    // --- Fused projection GEMMs ---
    GemmBatch gp;
    gp.As[0] = (const __half*)xq; gp.As[1] = (const __half*)xk;
    gp.As[2] = (const __half*)xv;
    gp.Bs[0] = (const __half*)wq;
    gp.Bs[1] = (const __half*)wk;
    gp.Bs[2] = (const __half*)wv;
    gp.bias[0] = bQ; gp.bias[1] = bK; gp.bias[2] = bV;
    gp.Yh[0] = (__half*)qb; gp.Yh[1] = (__half*)kb; gp.Yh[2] = (__half*)vb;
    gemm_proj_kernel<<<dim3(Cc / 128, Mc / 256, 3), 256, G_SMEM_TOTAL>>>(gp);

    dim3 attn_grid(Lc / 256, Bc * Hc);
    attn_mma_kernel<<<attn_grid, 256, ATT_SMEM>>>(
        (const __half*)qb, (const __half*)kb, (const __half*)vb,
        (const __nv_bfloat16*)pM, (__half*)zz);

    gemm_out_kernel<<<dim3(Cc / 128, Mc / 256), 256, G_SMEM_TOTAL>>>(
        (const __half*)zz, (const __half*)wo, bO, out);
}